// round 1
// baseline (speedup 1.0000x reference)
#include <cuda_runtime.h>
#include <math.h>

#define BB 32
#define TT 4096
#define DIN 256
#define HID 512
#define AD 259
#define KLIFT 64
#define DMODEL 1024
#define KSEL 32
#define PGD_STEPS 60
#define BISECT 30

// scratch (no allocations allowed)
__device__ float g_sal[BB * TT];
__device__ float g_xpart[16 * BB * DIN];
__device__ float g_xmean[BB * DIN];
__device__ float g_msal[BB];
__device__ int   g_topidx[BB * KSEL];

// ---------------------------------------------------------------------------
// Kernel 1: sal[b,t] = softplus( tanh(x@W1 + b1) . w_sal + b_sal )
// GEMM: M=131072, N=512, K=256, fp32. CTA tile M=32 x N=512.
// Each warp owns 4 rows (all 512 cols split across lanes), so the saliency
// dot-reduction over N is a pure warp shuffle reduce.
// ---------------------------------------------------------------------------
__global__ __launch_bounds__(256) void k_gemm_sal(
    const float* __restrict__ x, const float* __restrict__ W1,
    const float* __restrict__ b1, const float* __restrict__ w_sal,
    const float* __restrict__ b_sal)
{
    __shared__ float As[16][32];
    __shared__ float Bs[16][512];
    const int tid = threadIdx.x;
    const int tx = tid & 31, ty = tid >> 5;
    const int m0 = blockIdx.x * 32;

    float acc[4][16];
#pragma unroll
    for (int i = 0; i < 4; i++)
#pragma unroll
        for (int j = 0; j < 16; j++) acc[i][j] = 0.f;

    for (int k0 = 0; k0 < 256; k0 += 16) {
        if (tid < 128) {
            int row = tid >> 2;
            int kq = (tid & 3) * 4;
            float4 v = *(const float4*)&x[(size_t)(m0 + row) * 256 + k0 + kq];
            As[kq + 0][row] = v.x; As[kq + 1][row] = v.y;
            As[kq + 2][row] = v.z; As[kq + 3][row] = v.w;
        }
#pragma unroll
        for (int it = 0; it < 8; it++) {
            int f = tid + it * 256;       // float4 index over 16x512 tile
            int k = f >> 7;
            int c4 = f & 127;
            *(float4*)&Bs[k][c4 * 4] =
                *(const float4*)&W1[(size_t)(k0 + k) * 512 + c4 * 4];
        }
        __syncthreads();
#pragma unroll
        for (int kk = 0; kk < 16; kk++) {
            float4 av = *(const float4*)&As[kk][ty * 4];
            float a[4] = {av.x, av.y, av.z, av.w};
#pragma unroll
            for (int jj = 0; jj < 4; jj++) {
                float4 bv = *(const float4*)&Bs[kk][tx * 4 + 128 * jj];
                float bq[4] = {bv.x, bv.y, bv.z, bv.w};
#pragma unroll
                for (int i = 0; i < 4; i++)
#pragma unroll
                    for (int q = 0; q < 4; q++)
                        acc[i][jj * 4 + q] = fmaf(a[i], bq[q], acc[i][jj * 4 + q]);
            }
        }
        __syncthreads();
    }

    // epilogue: tanh, dot with w_sal over this thread's 16 cols, warp-reduce
    float p[4] = {0.f, 0.f, 0.f, 0.f};
#pragma unroll
    for (int jj = 0; jj < 4; jj++) {
#pragma unroll
        for (int q = 0; q < 4; q++) {
            int c = tx * 4 + 128 * jj + q;
            float w = w_sal[c];
            float bb = b1[c];
#pragma unroll
            for (int i = 0; i < 4; i++)
                p[i] += tanhf(acc[i][jj * 4 + q] + bb) * w;
        }
    }
#pragma unroll
    for (int i = 0; i < 4; i++) {
        float v = p[i];
        for (int o = 16; o; o >>= 1) v += __shfl_down_sync(0xffffffffu, v, o);
        if (tx == 0) {
            float z = v + b_sal[0];
            float sp = fmaxf(z, 0.f) + log1pf(expf(-fabsf(z)));
            g_sal[m0 + ty * 4 + i] = sp;
        }
    }
}

// ---------------------------------------------------------------------------
// Kernel 2a/2b: mean of x over T per batch (deterministic two-stage)
// ---------------------------------------------------------------------------
__global__ void k_xmean_part(const float* __restrict__ x)
{
    int b = blockIdx.x, ch = blockIdx.y, d = threadIdx.x;
    const float* base = x + ((size_t)b * TT + ch * 256) * DIN + d;
    float acc = 0.f;
    for (int t = 0; t < 256; t++) acc += base[(size_t)t * DIN];
    g_xpart[(ch * BB + b) * DIN + d] = acc;
}

__global__ void k_xmean_fin()
{
    int b = blockIdx.x, d = threadIdx.x;
    float acc = 0.f;
    for (int ch = 0; ch < 16; ch++) acc += g_xpart[(ch * BB + b) * DIN + d];
    g_xmean[b * DIN + d] = acc * (1.0f / TT);
}

// ---------------------------------------------------------------------------
// Kernel 3: PGD selector (60 steps x 30-step bisection projection),
// + writes y_star into output, + mean_sal, + exact top-32 (ties -> lower idx).
// One CTA (1024 threads) per batch row; each thread owns 4 contiguous elems.
// ---------------------------------------------------------------------------
__global__ __launch_bounds__(1024) void k_selector(float* __restrict__ d_out)
{
    __shared__ float ysm[TT];
    __shared__ float red[33];
    __shared__ float red2[33];
    __shared__ int   redi[33];

    const int b = blockIdx.x;
    const int tid = threadIdx.x;
    const int lane = tid & 31, wid = tid >> 5;
    const int i0 = tid * 4;

    float4 sv = *(const float4*)&g_sal[b * TT + i0];
    float s[4] = {sv.x, sv.y, sv.z, sv.w};
    float y[4] = {0.0078125f, 0.0078125f, 0.0078125f, 0.0078125f};
    ysm[i0] = y[0]; ysm[i0 + 1] = y[1]; ysm[i0 + 2] = y[2]; ysm[i0 + 3] = y[3];
    __syncthreads();

    for (int step = 0; step < PGD_STEPS; step++) {
        float l1 = (i0 > 0) ? ysm[i0 - 1] : 0.f;
        float l2 = (i0 > 1) ? ysm[i0 - 2] : 0.f;
        float r1 = (i0 + 4 < TT) ? ysm[i0 + 4] : 0.f;
        float r2 = (i0 + 5 < TT) ? ysm[i0 + 5] : 0.f;
        // neighbor sums in reference addition order: (((+1) + (-1)) + (+2)) + (-2)
        float nb[4];
        nb[0] = ((y[1] + l1) + y[2]) + l2;
        nb[1] = ((y[2] + y[0]) + y[3]) + l1;
        nb[2] = ((y[3] + y[1]) + r1) + y[0];
        nb[3] = ((r1 + y[2]) + r2) + y[1];

        float z[4], lsum = 0.f, lmax = 0.f;
#pragma unroll
        for (int q = 0; q < 4; q++) {
            float g = (s[q] - y[q]) - 0.5f * nb[q];   // 2*lam=1, lam=0.5
            float zz = y[q] + 0.1f * g;               // eta=0.1
            zz = fminf(fmaxf(zz, 0.f), 1.f);
            z[q] = zz;
            lsum += zz;
            lmax = fmaxf(lmax, zz);
        }

        // fused block reduce: sum + max
        float vs = lsum, vm = lmax;
        for (int o = 16; o; o >>= 1) {
            vs += __shfl_down_sync(0xffffffffu, vs, o);
            vm = fmaxf(vm, __shfl_down_sync(0xffffffffu, vm, o));
        }
        if (lane == 0) { red[wid] = vs; red2[wid] = vm; }
        __syncthreads();
        if (wid == 0) {
            vs = red[lane]; vm = red2[lane];
            for (int o = 16; o; o >>= 1) {
                vs += __shfl_down_sync(0xffffffffu, vs, o);
                vm = fmaxf(vm, __shfl_down_sync(0xffffffffu, vm, o));
            }
            if (lane == 0) { red[32] = vs; red2[32] = vm; }
        }
        __syncthreads();
        float total = red[32];
        float mx = red2[32];

        float tau = 0.f;
        if (total > 32.0f) {                 // uniform branch
            float lo = 0.f, hi = mx;
            for (int it = 0; it < BISECT; it++) {
                float mid = 0.5f * (lo + hi);
                float ls = 0.f;
#pragma unroll
                for (int q = 0; q < 4; q++)
                    ls += fminf(fmaxf(z[q] - mid, 0.f), 1.f);
                for (int o = 16; o; o >>= 1) ls += __shfl_down_sync(0xffffffffu, ls, o);
                if (lane == 0) red[wid] = ls;
                __syncthreads();
                if (wid == 0) {
                    float v = red[lane];
                    for (int o = 16; o; o >>= 1) v += __shfl_down_sync(0xffffffffu, v, o);
                    if (lane == 0) red[32] = v;
                }
                __syncthreads();
                float ssum = red[32];
                if (ssum > 32.0f) lo = mid; else hi = mid;
            }
            tau = 0.5f * (lo + hi);
        }
#pragma unroll
        for (int q = 0; q < 4; q++)
            y[q] = fminf(fmaxf(z[q] - tau, 0.f), 1.f);
        __syncthreads();
        ysm[i0] = y[0]; ysm[i0 + 1] = y[1]; ysm[i0 + 2] = y[2]; ysm[i0 + 3] = y[3];
        __syncthreads();
    }

    // ---- write y_star to output (after tokens region) ----
    float* outY = d_out + (size_t)BB * KSEL * DMODEL + (size_t)b * TT;
    *(float4*)&outY[i0] = make_float4(y[0], y[1], y[2], y[3]);

    // ---- mean_sal ----
    {
        float ms = ((s[0] + s[1]) + s[2]) + s[3];
        for (int o = 16; o; o >>= 1) ms += __shfl_down_sync(0xffffffffu, ms, o);
        if (lane == 0) red[wid] = ms;
        __syncthreads();
        if (wid == 0) {
            float v = red[lane];
            for (int o = 16; o; o >>= 1) v += __shfl_down_sync(0xffffffffu, v, o);
            if (lane == 0) g_msal[b] = v * (1.0f / TT);
        }
        __syncthreads();
    }

    // ---- top-32 iterative argmax (exact top_k order: value desc, index asc) ----
    float mval[4] = {y[0], y[1], y[2], y[3]};
    for (int sel = 0; sel < KSEL; sel++) {
        float bv = -1.f; int bi = TT;
#pragma unroll
        for (int q = 0; q < 4; q++) {
            if (mval[q] > bv) { bv = mval[q]; bi = i0 + q; }   // ascending q: ties keep lower idx
        }
        for (int o = 16; o; o >>= 1) {
            float ov = __shfl_down_sync(0xffffffffu, bv, o);
            int   oi = __shfl_down_sync(0xffffffffu, bi, o);
            if (ov > bv || (ov == bv && oi < bi)) { bv = ov; bi = oi; }
        }
        if (lane == 0) { red[wid] = bv; redi[wid] = bi; }
        __syncthreads();
        if (wid == 0) {
            bv = red[lane]; bi = redi[lane];
            for (int o = 16; o; o >>= 1) {
                float ov = __shfl_down_sync(0xffffffffu, bv, o);
                int   oi = __shfl_down_sync(0xffffffffu, bi, o);
                if (ov > bv || (ov == bv && oi < bi)) { bv = ov; bi = oi; }
            }
            if (lane == 0) { redi[32] = bi; g_topidx[b * KSEL + sel] = bi; }
        }
        __syncthreads();
        int win = redi[32];
        if ((win >> 2) == tid) mval[win & 3] = -1.f;
        // no extra sync needed: next iteration's writes go to redi[0..31] only,
        // and redi[32] is rewritten only after the next __syncthreads.
    }
}

// ---------------------------------------------------------------------------
// Kernel 4: gather selected rows -> build centered/normalized anchor vector ->
// lift (259->64) -> project (64->1024). One CTA per (b, j).
// ---------------------------------------------------------------------------
__global__ __launch_bounds__(256) void k_tokens(
    const float* __restrict__ x, const float* __restrict__ mu,
    const float* __restrict__ sigma, const float* __restrict__ W_lift,
    const float* __restrict__ b_lift, const float* __restrict__ W_proj,
    const float* __restrict__ b_proj, float* __restrict__ out)
{
    __shared__ float u[AD];
    __shared__ float lf[KLIFT];
    const int b = blockIdx.x, j = blockIdx.y;
    const int tid = threadIdx.x;
    const int idx = g_topidx[b * KSEL + j];

    {
        float v = x[((size_t)b * TT + idx) * DIN + tid] - g_xmean[b * DIN + tid];
        u[tid] = (v - mu[tid]) / sigma[tid];
    }
    if (tid == 0) {
        float sali = g_sal[b * TT + idx];
        float ms = g_msal[b];
        u[256] = ((sali - ms) - mu[256]) / sigma[256];
        float tn = (float)idx * (1.0f / 4096.0f);
        u[257] = ((tn - 0.4998779296875f) - mu[257]) / sigma[257];   // mean(t/T) exact
        float ds = (idx == 0) ? 0.f : (sali - g_sal[b * TT + idx - 1]);
        float mds = (g_sal[b * TT + TT - 1] - g_sal[b * TT]) * (1.0f / 4096.0f);
        u[258] = ((ds - mds) - mu[258]) / sigma[258];
    }
    __syncthreads();

    if (tid < KLIFT) {
        float acc = b_lift[tid];
        for (int d = 0; d < AD; d++)
            acc = fmaf(u[d], W_lift[d * KLIFT + tid], acc);
        lf[tid] = acc;
    }
    __syncthreads();

    float* o = out + ((size_t)(b * KSEL + j)) * DMODEL;
    for (int m = tid; m < DMODEL; m += 256) {
        float acc = b_proj[m];
#pragma unroll
        for (int k = 0; k < KLIFT; k++)
            acc = fmaf(lf[k], W_proj[k * DMODEL + m], acc);
        o[m] = acc;
    }
}

// ---------------------------------------------------------------------------
extern "C" void kernel_launch(void* const* d_in, const int* in_sizes, int n_in,
                              void* d_out, int out_size)
{
    const float* x      = (const float*)d_in[0];
    const float* W1     = (const float*)d_in[1];
    const float* b1     = (const float*)d_in[2];
    // d_in[3] = w_event, d_in[4] = b_event : dead (not in outputs)
    const float* w_sal  = (const float*)d_in[5];
    const float* b_sal  = (const float*)d_in[6];
    const float* mu     = (const float*)d_in[7];
    const float* sigma  = (const float*)d_in[8];
    const float* W_lift = (const float*)d_in[9];
    const float* b_lift = (const float*)d_in[10];
    const float* W_proj = (const float*)d_in[11];
    const float* b_proj = (const float*)d_in[12];
    float* out = (float*)d_out;

    k_gemm_sal<<<(BB * TT) / 32, 256>>>(x, W1, b1, w_sal, b_sal);
    k_xmean_part<<<dim3(BB, 16), 256>>>(x);
    k_xmean_fin<<<BB, 256>>>();
    k_selector<<<BB, 1024>>>(out);
    k_tokens<<<dim3(BB, KSEL), 256>>>(x, mu, sigma, W_lift, b_lift, W_proj, b_proj, out);
}

// round 4
// speedup vs baseline: 1.9379x; 1.9379x over previous
#include <cuda_runtime.h>
#include <cuda_bf16.h>
#include <cstdint>
#include <math.h>

#define BB 32
#define TT 4096
#define DIN 256
#define HID 512
#define AD 259
#define KLIFT 64
#define DMODEL 1024
#define KSEL 32
#define PGD_STEPS 60

// ---------------- scratch (device globals; no allocation allowed) ----------
__device__ float g_sal[BB * TT];
__device__ float g_spart[4][BB * TT];        // per-N-tile partial saliency dot
__device__ float g_xpart[16 * BB * DIN];
__device__ float g_xmean[BB * DIN];
__device__ float g_msal[BB];
__device__ int   g_topidx[BB * KSEL];
__device__ __nv_bfloat16 g_Bhi[HID * DIN];   // W1^T bf16 hi  [512][256]
__device__ __nv_bfloat16 g_Blo[HID * DIN];   // W1^T bf16 lo

__device__ __forceinline__ uint32_t pack_bf2(__nv_bfloat16 a, __nv_bfloat16 b) {
    return (uint32_t)__bfloat16_as_ushort(a) | ((uint32_t)__bfloat16_as_ushort(b) << 16);
}

// mma.sync m16n8k16 row.col f32.bf16.bf16.f32 (portable PTX, HMMA pipe)
__device__ __forceinline__ void mma_bf16(float* d, const uint32_t* a, const uint32_t* b) {
    asm volatile(
        "mma.sync.aligned.m16n8k16.row.col.f32.bf16.bf16.f32 "
        "{%0,%1,%2,%3}, {%4,%5,%6,%7}, {%8,%9}, {%0,%1,%2,%3};"
        : "+f"(d[0]), "+f"(d[1]), "+f"(d[2]), "+f"(d[3])
        : "r"(a[0]), "r"(a[1]), "r"(a[2]), "r"(a[3]), "r"(b[0]), "r"(b[1]));
}

// ---------------------------------------------------------------------------
// Kernel 0: split W1 -> transposed bf16 hi/lo  B[n][k] = W1[k][n]
// ---------------------------------------------------------------------------
__global__ void k_convert_w(const float* __restrict__ W1)
{
    int n = blockIdx.x, k = threadIdx.x;
    float v = W1[(size_t)k * HID + n];
    __nv_bfloat16 h = __float2bfloat16(v);
    float r = v - __bfloat162float(h);
    g_Bhi[n * DIN + k] = h;
    g_Blo[n * DIN + k] = __float2bfloat16(r);
}

// ---------------------------------------------------------------------------
// Kernel 1: bf16-split GEMM via mma.sync (3 terms: AhBh + AlBh + AhBl)
// CTA tile M=128 x N=128, K=256 in 16 chunks of 16, double-buffered smem.
// Epilogue: partial = sum_n tanh(h + b1[n]) * w_sal[n] over this N-tile.
// ---------------------------------------------------------------------------
__global__ __launch_bounds__(256) void k_gemm_part(
    const float* __restrict__ x, const float* __restrict__ b1,
    const float* __restrict__ w_sal)
{
    __shared__ __align__(16) __nv_bfloat16 sAh[2][128 * 16];
    __shared__ __align__(16) __nv_bfloat16 sAl[2][128 * 16];
    __shared__ __align__(16) __nv_bfloat16 sBh[2][128 * 16];
    __shared__ __align__(16) __nv_bfloat16 sBl[2][128 * 16];
    __shared__ float part[4][128];
    __shared__ float sB1[128], sWs[128];

    const int tid = threadIdx.x;
    const int m0 = blockIdx.x * 128;
    const int n0 = blockIdx.y * 128;
    const int lane = tid & 31, wid = tid >> 5;
    const int wm = (wid >> 2) * 64, wn = (wid & 3) * 32;
    const int g = lane >> 2, t = lane & 3;

    if (tid < 128) { sB1[tid] = b1[n0 + tid]; sWs[tid] = w_sal[n0 + tid]; }

    const int arow = tid >> 1, ahalf = tid & 1;   // load mapping: half-row of 8

    float acc[4][4][4];
#pragma unroll
    for (int mi = 0; mi < 4; mi++)
#pragma unroll
        for (int ni = 0; ni < 4; ni++)
#pragma unroll
            for (int q = 0; q < 4; q++) acc[mi][ni][q] = 0.f;

    // global prefetch registers
    float4 pa0, pa1;
    uint4 pbh, pbl;
    {
        const float* ap = &x[(size_t)(m0 + arow) * DIN + ahalf * 8];
        pa0 = *(const float4*)(ap);
        pa1 = *(const float4*)(ap + 4);
        pbh = *(const uint4*)&g_Bhi[(n0 + arow) * DIN + ahalf * 8];
        pbl = *(const uint4*)&g_Blo[(n0 + arow) * DIN + ahalf * 8];
    }

    for (int s = 0; s < 16; s++) {
        const int buf = s & 1;
        // ---- STS prefetched tile (split A on the fly) ----
        {
            float f[8] = {pa0.x, pa0.y, pa0.z, pa0.w, pa1.x, pa1.y, pa1.z, pa1.w};
            uint32_t hw[4], lw[4];
#pragma unroll
            for (int q = 0; q < 4; q++) {
                __nv_bfloat16 h0 = __float2bfloat16(f[q * 2]);
                __nv_bfloat16 h1 = __float2bfloat16(f[q * 2 + 1]);
                __nv_bfloat16 l0 = __float2bfloat16(f[q * 2] - __bfloat162float(h0));
                __nv_bfloat16 l1 = __float2bfloat16(f[q * 2 + 1] - __bfloat162float(h1));
                hw[q] = pack_bf2(h0, h1);
                lw[q] = pack_bf2(l0, l1);
            }
            int soff = arow * 16 + ahalf * 8;
            *(uint4*)&sAh[buf][soff] = make_uint4(hw[0], hw[1], hw[2], hw[3]);
            *(uint4*)&sAl[buf][soff] = make_uint4(lw[0], lw[1], lw[2], lw[3]);
            *(uint4*)&sBh[buf][soff] = pbh;
            *(uint4*)&sBl[buf][soff] = pbl;
        }
        __syncthreads();
        // ---- prefetch next chunk ----
        if (s < 15) {
            const float* ap = &x[(size_t)(m0 + arow) * DIN + (s + 1) * 16 + ahalf * 8];
            pa0 = *(const float4*)(ap);
            pa1 = *(const float4*)(ap + 4);
            pbh = *(const uint4*)&g_Bhi[(n0 + arow) * DIN + (s + 1) * 16 + ahalf * 8];
            pbl = *(const uint4*)&g_Blo[(n0 + arow) * DIN + (s + 1) * 16 + ahalf * 8];
        }
        // ---- fragments + 3 mma passes ----
        const __nv_bfloat16* Ah = sAh[buf];
        const __nv_bfloat16* Al = sAl[buf];
        const __nv_bfloat16* Bh = sBh[buf];
        const __nv_bfloat16* Bl = sBl[buf];

        uint32_t ah[4][4], bh[4][2], bl[4][2], al[4][4];
#pragma unroll
        for (int mi = 0; mi < 4; mi++) {
            int r0 = (wm + mi * 16 + g) * 16;
            int r1 = r0 + 8 * 16;
            ah[mi][0] = *(const uint32_t*)&Ah[r0 + t * 2];
            ah[mi][1] = *(const uint32_t*)&Ah[r1 + t * 2];
            ah[mi][2] = *(const uint32_t*)&Ah[r0 + 8 + t * 2];
            ah[mi][3] = *(const uint32_t*)&Ah[r1 + 8 + t * 2];
        }
#pragma unroll
        for (int ni = 0; ni < 4; ni++) {
            int rb = (wn + ni * 8 + g) * 16;
            bh[ni][0] = *(const uint32_t*)&Bh[rb + t * 2];
            bh[ni][1] = *(const uint32_t*)&Bh[rb + 8 + t * 2];
        }
#pragma unroll
        for (int mi = 0; mi < 4; mi++)
#pragma unroll
            for (int ni = 0; ni < 4; ni++)
                mma_bf16(acc[mi][ni], ah[mi], bh[ni]);
#pragma unroll
        for (int ni = 0; ni < 4; ni++) {
            int rb = (wn + ni * 8 + g) * 16;
            bl[ni][0] = *(const uint32_t*)&Bl[rb + t * 2];
            bl[ni][1] = *(const uint32_t*)&Bl[rb + 8 + t * 2];
        }
#pragma unroll
        for (int mi = 0; mi < 4; mi++)
#pragma unroll
            for (int ni = 0; ni < 4; ni++)
                mma_bf16(acc[mi][ni], ah[mi], bl[ni]);
#pragma unroll
        for (int mi = 0; mi < 4; mi++) {
            int r0 = (wm + mi * 16 + g) * 16;
            int r1 = r0 + 8 * 16;
            al[mi][0] = *(const uint32_t*)&Al[r0 + t * 2];
            al[mi][1] = *(const uint32_t*)&Al[r1 + t * 2];
            al[mi][2] = *(const uint32_t*)&Al[r0 + 8 + t * 2];
            al[mi][3] = *(const uint32_t*)&Al[r1 + 8 + t * 2];
        }
#pragma unroll
        for (int mi = 0; mi < 4; mi++)
#pragma unroll
            for (int ni = 0; ni < 4; ni++)
                mma_bf16(acc[mi][ni], al[mi], bh[ni]);
        __syncthreads();
    }

    // ---- epilogue: tanh + w_sal dot over this CTA's 128 columns ----
    float rsum[4][2];
#pragma unroll
    for (int mi = 0; mi < 4; mi++) { rsum[mi][0] = 0.f; rsum[mi][1] = 0.f; }
#pragma unroll
    for (int mi = 0; mi < 4; mi++)
#pragma unroll
        for (int ni = 0; ni < 4; ni++) {
            int c0 = wn + ni * 8 + t * 2;
            float w0 = sWs[c0], w1 = sWs[c0 + 1];
            float bb0 = sB1[c0], bb1 = sB1[c0 + 1];
            rsum[mi][0] += tanhf(acc[mi][ni][0] + bb0) * w0
                         + tanhf(acc[mi][ni][1] + bb1) * w1;
            rsum[mi][1] += tanhf(acc[mi][ni][2] + bb0) * w0
                         + tanhf(acc[mi][ni][3] + bb1) * w1;
        }
#pragma unroll
    for (int mi = 0; mi < 4; mi++)
#pragma unroll
        for (int sel = 0; sel < 2; sel++) {
            float v = rsum[mi][sel];
            v += __shfl_xor_sync(0xffffffffu, v, 1);
            v += __shfl_xor_sync(0xffffffffu, v, 2);
            if (t == 0) part[wid & 3][wm + mi * 16 + sel * 8 + g] = v;
        }
    __syncthreads();
    if (tid < 128) {
        float v = ((part[0][tid] + part[1][tid]) + part[2][tid]) + part[3][tid];
        g_spart[blockIdx.y][m0 + tid] = v;
    }
}

// combine 4 N-tile partials -> saliency
__global__ void k_sal_fin(const float* __restrict__ b_sal)
{
    int i = blockIdx.x * 256 + threadIdx.x;
    float z = ((g_spart[0][i] + g_spart[1][i]) + g_spart[2][i]) + g_spart[3][i]
              + b_sal[0];
    g_sal[i] = fmaxf(z, 0.f) + log1pf(expf(-fabsf(z)));
}

// ---------------------------------------------------------------------------
// Kernel 2a/2b: mean of x over T per batch (deterministic two-stage)
// ---------------------------------------------------------------------------
__global__ void k_xmean_part(const float* __restrict__ x)
{
    int b = blockIdx.x, ch = blockIdx.y, d = threadIdx.x;
    const float* base = x + ((size_t)b * TT + ch * 256) * DIN + d;
    float acc = 0.f;
    for (int t = 0; t < 256; t++) acc += base[(size_t)t * DIN];
    g_xpart[(ch * BB + b) * DIN + d] = acc;
}
__global__ void k_xmean_fin()
{
    int b = blockIdx.x, d = threadIdx.x;
    float acc = 0.f;
    for (int ch = 0; ch < 16; ch++) acc += g_xpart[(ch * BB + b) * DIN + d];
    g_xmean[b * DIN + d] = acc * (1.0f / TT);
}

// ---------------------------------------------------------------------------
// Kernel 3: PGD selector; projection tau via exact waterfilling (Michelot).
// Double-buffered y. Then y_star out, mean_sal, exact top-32.
// ---------------------------------------------------------------------------
__global__ __launch_bounds__(1024) void k_selector(float* __restrict__ d_out)
{
    __shared__ float ysA[TT];
    __shared__ float ysB[TT];
    __shared__ float redS[32], redC[32];
    __shared__ float bc[2];
    __shared__ float redT[33];
    __shared__ int   redi[33];

    const int b = blockIdx.x;
    const int tid = threadIdx.x;
    const int lane = tid & 31, wid = tid >> 5;
    const int i0 = tid * 4;

    float4 sv = *(const float4*)&g_sal[b * TT + i0];
    float s[4] = {sv.x, sv.y, sv.z, sv.w};
    float y[4] = {0.0078125f, 0.0078125f, 0.0078125f, 0.0078125f};
    ysA[i0] = y[0]; ysA[i0 + 1] = y[1]; ysA[i0 + 2] = y[2]; ysA[i0 + 3] = y[3];
    __syncthreads();

    for (int step = 0; step < PGD_STEPS; step++) {
        const float* rd = (step & 1) ? ysB : ysA;
        float*       wr = (step & 1) ? ysA : ysB;
        float l1 = (i0 > 0) ? rd[i0 - 1] : 0.f;
        float l2 = (i0 > 0) ? rd[i0 - 2] : 0.f;
        float r1 = (i0 + 4 < TT) ? rd[i0 + 4] : 0.f;
        float r2 = (i0 + 4 < TT) ? rd[i0 + 5] : 0.f;
        float nb[4];
        nb[0] = ((y[1] + l1) + y[2]) + l2;
        nb[1] = ((y[2] + y[0]) + y[3]) + l1;
        nb[2] = ((y[3] + y[1]) + r1) + y[0];
        nb[3] = ((r1 + y[2]) + r2) + y[1];

        float z[4];
#pragma unroll
        for (int q = 0; q < 4; q++) {
            float g = (s[q] - y[q]) - 0.5f * nb[q];
            z[q] = fminf(fmaxf(y[q] + 0.1f * g, 0.f), 1.f);
        }

        float tau = 0.f;
        for (int it = 0; it < 48; it++) {
            float ls = 0.f, lc = 0.f;
#pragma unroll
            for (int q = 0; q < 4; q++)
                if (z[q] > tau) { ls += z[q]; lc += 1.f; }
            for (int o = 16; o; o >>= 1) {
                ls += __shfl_down_sync(0xffffffffu, ls, o);
                lc += __shfl_down_sync(0xffffffffu, lc, o);
            }
            if (lane == 0) { redS[wid] = ls; redC[wid] = lc; }
            __syncthreads();
            if (wid == 0) {
                float vs = redS[lane], vc = redC[lane];
                for (int o = 16; o; o >>= 1) {
                    vs += __shfl_down_sync(0xffffffffu, vs, o);
                    vc += __shfl_down_sync(0xffffffffu, vc, o);
                }
                if (lane == 0) { bc[0] = vs; bc[1] = vc; }
            }
            __syncthreads();
            float S = bc[0], C = bc[1];
            if (it == 0 && S <= 32.f) break;
            if (C < 1.f) break;
            float tnew = (S - 32.f) / C;
            if (!(tnew > tau)) break;
            tau = tnew;
        }
#pragma unroll
        for (int q = 0; q < 4; q++)
            y[q] = fminf(fmaxf(z[q] - tau, 0.f), 1.f);
        wr[i0] = y[0]; wr[i0 + 1] = y[1]; wr[i0 + 2] = y[2]; wr[i0 + 3] = y[3];
        __syncthreads();
    }

    // ---- y_star out ----
    float* outY = d_out + (size_t)BB * KSEL * DMODEL + (size_t)b * TT;
    *(float4*)&outY[i0] = make_float4(y[0], y[1], y[2], y[3]);

    // ---- mean_sal ----
    {
        float ms = ((s[0] + s[1]) + s[2]) + s[3];
        for (int o = 16; o; o >>= 1) ms += __shfl_down_sync(0xffffffffu, ms, o);
        if (lane == 0) redT[wid] = ms;
        __syncthreads();
        if (wid == 0) {
            float v = redT[lane];
            for (int o = 16; o; o >>= 1) v += __shfl_down_sync(0xffffffffu, v, o);
            if (lane == 0) g_msal[b] = v * (1.0f / TT);
        }
        __syncthreads();
    }

    // ---- top-32 iterative argmax (value desc, index asc on ties) ----
    float mval[4] = {y[0], y[1], y[2], y[3]};
    for (int sel = 0; sel < KSEL; sel++) {
        float bv = -1.f; int bi = TT;
#pragma unroll
        for (int q = 0; q < 4; q++)
            if (mval[q] > bv) { bv = mval[q]; bi = i0 + q; }
        for (int o = 16; o; o >>= 1) {
            float ov = __shfl_down_sync(0xffffffffu, bv, o);
            int   oi = __shfl_down_sync(0xffffffffu, bi, o);
            if (ov > bv || (ov == bv && oi < bi)) { bv = ov; bi = oi; }
        }
        if (lane == 0) { redT[wid] = bv; redi[wid] = bi; }
        __syncthreads();
        if (wid == 0) {
            bv = redT[lane]; bi = redi[lane];
            for (int o = 16; o; o >>= 1) {
                float ov = __shfl_down_sync(0xffffffffu, bv, o);
                int   oi = __shfl_down_sync(0xffffffffu, bi, o);
                if (ov > bv || (ov == bv && oi < bi)) { bv = ov; bi = oi; }
            }
            if (lane == 0) { redi[32] = bi; g_topidx[b * KSEL + sel] = bi; }
        }
        __syncthreads();
        int win = redi[32];
        if ((win >> 2) == tid) mval[win & 3] = -1.f;
    }
}

// ---------------------------------------------------------------------------
// Kernel 4: gather -> anchor vector -> lift (259->64) -> project (64->1024)
// ---------------------------------------------------------------------------
__global__ __launch_bounds__(256) void k_tokens(
    const float* __restrict__ x, const float* __restrict__ mu,
    const float* __restrict__ sigma, const float* __restrict__ W_lift,
    const float* __restrict__ b_lift, const float* __restrict__ W_proj,
    const float* __restrict__ b_proj, float* __restrict__ out)
{
    __shared__ float u[AD];
    __shared__ float lf[KLIFT];
    const int b = blockIdx.x, j = blockIdx.y;
    const int tid = threadIdx.x;
    const int idx = g_topidx[b * KSEL + j];

    {
        float v = x[((size_t)b * TT + idx) * DIN + tid] - g_xmean[b * DIN + tid];
        u[tid] = (v - mu[tid]) / sigma[tid];
    }
    if (tid == 0) {
        float sali = g_sal[b * TT + idx];
        float ms = g_msal[b];
        u[256] = ((sali - ms) - mu[256]) / sigma[256];
        float tn = (float)idx * (1.0f / 4096.0f);
        u[257] = ((tn - 0.4998779296875f) - mu[257]) / sigma[257];
        float ds = (idx == 0) ? 0.f : (sali - g_sal[b * TT + idx - 1]);
        float mds = (g_sal[b * TT + TT - 1] - g_sal[b * TT]) * (1.0f / 4096.0f);
        u[258] = ((ds - mds) - mu[258]) / sigma[258];
    }
    __syncthreads();

    if (tid < KLIFT) {
        float acc = b_lift[tid];
        for (int d = 0; d < AD; d++)
            acc = fmaf(u[d], W_lift[d * KLIFT + tid], acc);
        lf[tid] = acc;
    }
    __syncthreads();

    float* o = out + ((size_t)(b * KSEL + j)) * DMODEL;
    for (int m = tid; m < DMODEL; m += 256) {
        float acc = b_proj[m];
#pragma unroll
        for (int k = 0; k < KLIFT; k++)
            acc = fmaf(lf[k], W_proj[k * DMODEL + m], acc);
        o[m] = acc;
    }
}

// ---------------------------------------------------------------------------
extern "C" void kernel_launch(void* const* d_in, const int* in_sizes, int n_in,
                              void* d_out, int out_size)
{
    const float* x      = (const float*)d_in[0];
    const float* W1     = (const float*)d_in[1];
    const float* b1     = (const float*)d_in[2];
    const float* w_sal  = (const float*)d_in[5];
    const float* b_sal  = (const float*)d_in[6];
    const float* mu     = (const float*)d_in[7];
    const float* sigma  = (const float*)d_in[8];
    const float* W_lift = (const float*)d_in[9];
    const float* b_lift = (const float*)d_in[10];
    const float* W_proj = (const float*)d_in[11];
    const float* b_proj = (const float*)d_in[12];
    float* out = (float*)d_out;

    k_convert_w<<<HID, DIN>>>(W1);
    k_gemm_part<<<dim3((BB * TT) / 128, 4), 256>>>(x, b1, w_sal);
    k_sal_fin<<<(BB * TT) / 256, 256>>>(b_sal);
    k_xmean_part<<<dim3(BB, 16), 256>>>(x);
    k_xmean_fin<<<BB, 256>>>();
    k_selector<<<BB, 1024>>>(out);
    k_tokens<<<dim3(BB, KSEL), 256>>>(x, mu, sigma, W_lift, b_lift, W_proj, b_proj, out);
}

// round 5
// speedup vs baseline: 2.3916x; 1.2341x over previous
#include <cuda_runtime.h>
#include <cuda_bf16.h>
#include <cstdint>
#include <math.h>

#define BB 32
#define TT 4096
#define DIN 256
#define HID 512
#define AD 259
#define KLIFT 64
#define DMODEL 1024
#define KSEL 32
#define PGD_STEPS 60

// ---------------- scratch (device globals; no allocation allowed) ----------
__device__ float g_sal[BB * TT];
__device__ float g_spart[4][BB * TT];        // per-N-tile partial saliency dot
__device__ float g_xpart[16 * BB * DIN];
__device__ float g_xmean[BB * DIN];
__device__ float g_msal[BB];
__device__ int   g_topidx[BB * KSEL];
__device__ __nv_bfloat16 g_Bhi[HID * DIN];   // W1^T bf16 hi  [512][256]
__device__ __nv_bfloat16 g_Blo[HID * DIN];   // W1^T bf16 lo

__device__ __forceinline__ uint32_t pack_bf2(__nv_bfloat16 a, __nv_bfloat16 b) {
    return (uint32_t)__bfloat16_as_ushort(a) | ((uint32_t)__bfloat16_as_ushort(b) << 16);
}

// mma.sync m16n8k16 row.col f32.bf16.bf16.f32 (portable PTX, HMMA pipe)
__device__ __forceinline__ void mma_bf16(float* d, const uint32_t* a, const uint32_t* b) {
    asm volatile(
        "mma.sync.aligned.m16n8k16.row.col.f32.bf16.bf16.f32 "
        "{%0,%1,%2,%3}, {%4,%5,%6,%7}, {%8,%9}, {%0,%1,%2,%3};"
        : "+f"(d[0]), "+f"(d[1]), "+f"(d[2]), "+f"(d[3])
        : "r"(a[0]), "r"(a[1]), "r"(a[2]), "r"(a[3]), "r"(b[0]), "r"(b[1]));
}

// ---------------------------------------------------------------------------
// Kernel 0: split W1 -> transposed bf16 hi/lo  B[n][k] = W1[k][n]
// ---------------------------------------------------------------------------
__global__ void k_convert_w(const float* __restrict__ W1)
{
    int n = blockIdx.x, k = threadIdx.x;
    float v = W1[(size_t)k * HID + n];
    __nv_bfloat16 h = __float2bfloat16(v);
    float r = v - __bfloat162float(h);
    g_Bhi[n * DIN + k] = h;
    g_Blo[n * DIN + k] = __float2bfloat16(r);
}

// ---------------------------------------------------------------------------
// Kernel 1: bf16-split GEMM via mma.sync (3 terms: AhBh + AlBh + AhBl)
// CTA tile M=128 x N=128, K=256 in 16 chunks of 16, double-buffered smem.
// Epilogue: partial = sum_n tanh(h + b1[n]) * w_sal[n] over this N-tile.
// ---------------------------------------------------------------------------
__global__ __launch_bounds__(256) void k_gemm_part(
    const float* __restrict__ x, const float* __restrict__ b1,
    const float* __restrict__ w_sal)
{
    __shared__ __align__(16) __nv_bfloat16 sAh[2][128 * 16];
    __shared__ __align__(16) __nv_bfloat16 sAl[2][128 * 16];
    __shared__ __align__(16) __nv_bfloat16 sBh[2][128 * 16];
    __shared__ __align__(16) __nv_bfloat16 sBl[2][128 * 16];
    __shared__ float part[4][128];
    __shared__ float sB1[128], sWs[128];

    const int tid = threadIdx.x;
    const int m0 = blockIdx.x * 128;
    const int n0 = blockIdx.y * 128;
    const int lane = tid & 31, wid = tid >> 5;
    const int wm = (wid >> 2) * 64, wn = (wid & 3) * 32;
    const int g = lane >> 2, t = lane & 3;

    if (tid < 128) { sB1[tid] = b1[n0 + tid]; sWs[tid] = w_sal[n0 + tid]; }

    const int arow = tid >> 1, ahalf = tid & 1;

    float acc[4][4][4];
#pragma unroll
    for (int mi = 0; mi < 4; mi++)
#pragma unroll
        for (int ni = 0; ni < 4; ni++)
#pragma unroll
            for (int q = 0; q < 4; q++) acc[mi][ni][q] = 0.f;

    float4 pa0, pa1;
    uint4 pbh, pbl;
    {
        const float* ap = &x[(size_t)(m0 + arow) * DIN + ahalf * 8];
        pa0 = *(const float4*)(ap);
        pa1 = *(const float4*)(ap + 4);
        pbh = *(const uint4*)&g_Bhi[(n0 + arow) * DIN + ahalf * 8];
        pbl = *(const uint4*)&g_Blo[(n0 + arow) * DIN + ahalf * 8];
    }

    for (int s = 0; s < 16; s++) {
        const int buf = s & 1;
        {
            float f[8] = {pa0.x, pa0.y, pa0.z, pa0.w, pa1.x, pa1.y, pa1.z, pa1.w};
            uint32_t hw[4], lw[4];
#pragma unroll
            for (int q = 0; q < 4; q++) {
                __nv_bfloat16 h0 = __float2bfloat16(f[q * 2]);
                __nv_bfloat16 h1 = __float2bfloat16(f[q * 2 + 1]);
                __nv_bfloat16 l0 = __float2bfloat16(f[q * 2] - __bfloat162float(h0));
                __nv_bfloat16 l1 = __float2bfloat16(f[q * 2 + 1] - __bfloat162float(h1));
                hw[q] = pack_bf2(h0, h1);
                lw[q] = pack_bf2(l0, l1);
            }
            int soff = arow * 16 + ahalf * 8;
            *(uint4*)&sAh[buf][soff] = make_uint4(hw[0], hw[1], hw[2], hw[3]);
            *(uint4*)&sAl[buf][soff] = make_uint4(lw[0], lw[1], lw[2], lw[3]);
            *(uint4*)&sBh[buf][soff] = pbh;
            *(uint4*)&sBl[buf][soff] = pbl;
        }
        __syncthreads();
        if (s < 15) {
            const float* ap = &x[(size_t)(m0 + arow) * DIN + (s + 1) * 16 + ahalf * 8];
            pa0 = *(const float4*)(ap);
            pa1 = *(const float4*)(ap + 4);
            pbh = *(const uint4*)&g_Bhi[(n0 + arow) * DIN + (s + 1) * 16 + ahalf * 8];
            pbl = *(const uint4*)&g_Blo[(n0 + arow) * DIN + (s + 1) * 16 + ahalf * 8];
        }
        const __nv_bfloat16* Ah = sAh[buf];
        const __nv_bfloat16* Al = sAl[buf];
        const __nv_bfloat16* Bh = sBh[buf];
        const __nv_bfloat16* Bl = sBl[buf];

        uint32_t ah[4][4], bh[4][2], bl[4][2], al[4][4];
#pragma unroll
        for (int mi = 0; mi < 4; mi++) {
            int r0 = (wm + mi * 16 + g) * 16;
            int r1 = r0 + 8 * 16;
            ah[mi][0] = *(const uint32_t*)&Ah[r0 + t * 2];
            ah[mi][1] = *(const uint32_t*)&Ah[r1 + t * 2];
            ah[mi][2] = *(const uint32_t*)&Ah[r0 + 8 + t * 2];
            ah[mi][3] = *(const uint32_t*)&Ah[r1 + 8 + t * 2];
        }
#pragma unroll
        for (int ni = 0; ni < 4; ni++) {
            int rb = (wn + ni * 8 + g) * 16;
            bh[ni][0] = *(const uint32_t*)&Bh[rb + t * 2];
            bh[ni][1] = *(const uint32_t*)&Bh[rb + 8 + t * 2];
        }
#pragma unroll
        for (int mi = 0; mi < 4; mi++)
#pragma unroll
            for (int ni = 0; ni < 4; ni++)
                mma_bf16(acc[mi][ni], ah[mi], bh[ni]);
#pragma unroll
        for (int ni = 0; ni < 4; ni++) {
            int rb = (wn + ni * 8 + g) * 16;
            bl[ni][0] = *(const uint32_t*)&Bl[rb + t * 2];
            bl[ni][1] = *(const uint32_t*)&Bl[rb + 8 + t * 2];
        }
#pragma unroll
        for (int mi = 0; mi < 4; mi++)
#pragma unroll
            for (int ni = 0; ni < 4; ni++)
                mma_bf16(acc[mi][ni], ah[mi], bl[ni]);
#pragma unroll
        for (int mi = 0; mi < 4; mi++) {
            int r0 = (wm + mi * 16 + g) * 16;
            int r1 = r0 + 8 * 16;
            al[mi][0] = *(const uint32_t*)&Al[r0 + t * 2];
            al[mi][1] = *(const uint32_t*)&Al[r1 + t * 2];
            al[mi][2] = *(const uint32_t*)&Al[r0 + 8 + t * 2];
            al[mi][3] = *(const uint32_t*)&Al[r1 + 8 + t * 2];
        }
#pragma unroll
        for (int mi = 0; mi < 4; mi++)
#pragma unroll
            for (int ni = 0; ni < 4; ni++)
                mma_bf16(acc[mi][ni], al[mi], bh[ni]);
        __syncthreads();
    }

    // ---- epilogue: tanh + w_sal dot over this CTA's 128 columns ----
    float rsum[4][2];
#pragma unroll
    for (int mi = 0; mi < 4; mi++) { rsum[mi][0] = 0.f; rsum[mi][1] = 0.f; }
#pragma unroll
    for (int mi = 0; mi < 4; mi++)
#pragma unroll
        for (int ni = 0; ni < 4; ni++) {
            int c0 = wn + ni * 8 + t * 2;
            float w0 = sWs[c0], w1 = sWs[c0 + 1];
            float bb0 = sB1[c0], bb1 = sB1[c0 + 1];
            rsum[mi][0] += tanhf(acc[mi][ni][0] + bb0) * w0
                         + tanhf(acc[mi][ni][1] + bb1) * w1;
            rsum[mi][1] += tanhf(acc[mi][ni][2] + bb0) * w0
                         + tanhf(acc[mi][ni][3] + bb1) * w1;
        }
#pragma unroll
    for (int mi = 0; mi < 4; mi++)
#pragma unroll
        for (int sel = 0; sel < 2; sel++) {
            float v = rsum[mi][sel];
            v += __shfl_xor_sync(0xffffffffu, v, 1);
            v += __shfl_xor_sync(0xffffffffu, v, 2);
            if (t == 0) part[wid & 3][wm + mi * 16 + sel * 8 + g] = v;
        }
    __syncthreads();
    if (tid < 128) {
        float v = ((part[0][tid] + part[1][tid]) + part[2][tid]) + part[3][tid];
        g_spart[blockIdx.y][m0 + tid] = v;
    }
}

// ---------------------------------------------------------------------------
// Kernel 2a/2b: mean of x over T per batch (deterministic two-stage)
// ---------------------------------------------------------------------------
__global__ void k_xmean_part(const float* __restrict__ x)
{
    int b = blockIdx.x, ch = blockIdx.y, d = threadIdx.x;
    const float* base = x + ((size_t)b * TT + ch * 256) * DIN + d;
    float acc = 0.f;
    for (int t = 0; t < 256; t++) acc += base[(size_t)t * DIN];
    g_xpart[(ch * BB + b) * DIN + d] = acc;
}
__global__ void k_xmean_fin()
{
    int b = blockIdx.x, d = threadIdx.x;
    float acc = 0.f;
    for (int ch = 0; ch < 16; ch++) acc += g_xpart[(ch * BB + b) * DIN + d];
    g_xmean[b * DIN + d] = acc * (1.0f / TT);
}

// ---------------------------------------------------------------------------
// Kernel 3: fused sal-finalize + PGD selector.
// tau via warm-started Newton on phi(t)=sum(z-t)_+ - K (exact root; matches
// 30-step bisection to <=1e-9). All block reduces are 1-sync: every warp
// redundantly reduces the 32 per-warp partials (double-buffered vs races).
// ---------------------------------------------------------------------------
__global__ __launch_bounds__(1024) void k_selector(
    const float* __restrict__ b_sal, float* __restrict__ d_out)
{
    __shared__ float ysA[TT];
    __shared__ float ysB[TT];
    __shared__ float redS[2][32], redC[2][32];
    __shared__ float redT[2][32];
    __shared__ int   redi[2][32];

    const int b = blockIdx.x;
    const int tid = threadIdx.x;
    const int lane = tid & 31, wid = tid >> 5;
    const int i0 = tid * 4;

    // ---- fused saliency finalize (was k_sal_fin) ----
    float4 p0 = *(const float4*)&g_spart[0][b * TT + i0];
    float4 p1 = *(const float4*)&g_spart[1][b * TT + i0];
    float4 p2 = *(const float4*)&g_spart[2][b * TT + i0];
    float4 p3 = *(const float4*)&g_spart[3][b * TT + i0];
    const float bs = b_sal[0];
    float s[4];
    {
        float z0 = ((p0.x + p1.x) + p2.x) + p3.x + bs;
        float z1 = ((p0.y + p1.y) + p2.y) + p3.y + bs;
        float z2 = ((p0.z + p1.z) + p2.z) + p3.z + bs;
        float z3 = ((p0.w + p1.w) + p2.w) + p3.w + bs;
        s[0] = fmaxf(z0, 0.f) + log1pf(expf(-fabsf(z0)));
        s[1] = fmaxf(z1, 0.f) + log1pf(expf(-fabsf(z1)));
        s[2] = fmaxf(z2, 0.f) + log1pf(expf(-fabsf(z2)));
        s[3] = fmaxf(z3, 0.f) + log1pf(expf(-fabsf(z3)));
    }
    *(float4*)&g_sal[b * TT + i0] = make_float4(s[0], s[1], s[2], s[3]);

    float y[4] = {0.0078125f, 0.0078125f, 0.0078125f, 0.0078125f};
    ysA[i0] = y[0]; ysA[i0 + 1] = y[1]; ysA[i0 + 2] = y[2]; ysA[i0 + 3] = y[3];
    __syncthreads();

    float tau_prev = 0.f;
    for (int step = 0; step < PGD_STEPS; step++) {
        const float* rd = (step & 1) ? ysB : ysA;
        float*       wr = (step & 1) ? ysA : ysB;
        float l1 = (i0 > 0) ? rd[i0 - 1] : 0.f;
        float l2 = (i0 > 0) ? rd[i0 - 2] : 0.f;
        float r1 = (i0 + 4 < TT) ? rd[i0 + 4] : 0.f;
        float r2 = (i0 + 4 < TT) ? rd[i0 + 5] : 0.f;
        float nb[4];
        nb[0] = ((y[1] + l1) + y[2]) + l2;
        nb[1] = ((y[2] + y[0]) + y[3]) + l1;
        nb[2] = ((y[3] + y[1]) + r1) + y[0];
        nb[3] = ((r1 + y[2]) + r2) + y[1];

        float z[4];
#pragma unroll
        for (int q = 0; q < 4; q++) {
            float g = (s[q] - y[q]) - 0.5f * nb[q];
            z[q] = fminf(fmaxf(y[q] + 0.1f * g, 0.f), 1.f);
        }

        // warm-started Newton; 1 sync per iteration
        float tau = tau_prev;
        for (int it = 0; it < 24; it++) {
            const int p = it & 1;
            float ls = 0.f, lc = 0.f;
#pragma unroll
            for (int q = 0; q < 4; q++)
                if (z[q] > tau) { ls += z[q]; lc += 1.f; }
#pragma unroll
            for (int o = 16; o; o >>= 1) {
                ls += __shfl_xor_sync(0xffffffffu, ls, o);
                lc += __shfl_xor_sync(0xffffffffu, lc, o);
            }
            if (lane == 0) { redS[p][wid] = ls; redC[p][wid] = lc; }
            __syncthreads();
            float S = redS[p][lane], C = redC[p][lane];
#pragma unroll
            for (int o = 16; o; o >>= 1) {
                S += __shfl_xor_sync(0xffffffffu, S, o);
                C += __shfl_xor_sync(0xffffffffu, C, o);
            }
            float tnew = (C >= 1.f) ? fmaxf((S - 32.f) / C, 0.f) : 0.f;
            if (tnew == tau) break;     // uniform across all threads
            tau = tnew;
        }
        tau_prev = tau;
#pragma unroll
        for (int q = 0; q < 4; q++)
            y[q] = fminf(fmaxf(z[q] - tau, 0.f), 1.f);
        wr[i0] = y[0]; wr[i0 + 1] = y[1]; wr[i0 + 2] = y[2]; wr[i0 + 3] = y[3];
        __syncthreads();
    }

    // ---- y_star out ----
    float* outY = d_out + (size_t)BB * KSEL * DMODEL + (size_t)b * TT;
    *(float4*)&outY[i0] = make_float4(y[0], y[1], y[2], y[3]);

    // ---- mean_sal (1-sync redundant reduce) ----
    {
        float ms = ((s[0] + s[1]) + s[2]) + s[3];
#pragma unroll
        for (int o = 16; o; o >>= 1) ms += __shfl_xor_sync(0xffffffffu, ms, o);
        if (lane == 0) redS[0][wid] = ms;
        __syncthreads();
        if (tid < 32) {
            float v = redS[0][lane];
#pragma unroll
            for (int o = 16; o; o >>= 1) v += __shfl_xor_sync(0xffffffffu, v, o);
            if (lane == 0) g_msal[b] = v * (1.0f / TT);
        }
        __syncthreads();
    }

    // ---- top-32 iterative argmax, 1 sync per round ----
    float mval[4] = {y[0], y[1], y[2], y[3]};
    for (int sel = 0; sel < KSEL; sel++) {
        const int p = sel & 1;
        float bv = -1.f; int bi = TT;
#pragma unroll
        for (int q = 0; q < 4; q++)
            if (mval[q] > bv) { bv = mval[q]; bi = i0 + q; }
#pragma unroll
        for (int o = 16; o; o >>= 1) {
            float ov = __shfl_xor_sync(0xffffffffu, bv, o);
            int   oi = __shfl_xor_sync(0xffffffffu, bi, o);
            if (ov > bv || (ov == bv && oi < bi)) { bv = ov; bi = oi; }
        }
        if (lane == 0) { redT[p][wid] = bv; redi[p][wid] = bi; }
        __syncthreads();
        bv = redT[p][lane]; bi = redi[p][lane];
#pragma unroll
        for (int o = 16; o; o >>= 1) {
            float ov = __shfl_xor_sync(0xffffffffu, bv, o);
            int   oi = __shfl_xor_sync(0xffffffffu, bi, o);
            if (ov > bv || (ov == bv && oi < bi)) { bv = ov; bi = oi; }
        }
        if (tid == 0) g_topidx[b * KSEL + sel] = bi;
        if ((bi >> 2) == tid) mval[bi & 3] = -1.f;
    }
}

// ---------------------------------------------------------------------------
// Kernel 4: gather -> anchor vector -> lift (259->64) -> project (64->1024)
// ---------------------------------------------------------------------------
__global__ __launch_bounds__(256) void k_tokens(
    const float* __restrict__ x, const float* __restrict__ mu,
    const float* __restrict__ sigma, const float* __restrict__ W_lift,
    const float* __restrict__ b_lift, const float* __restrict__ W_proj,
    const float* __restrict__ b_proj, float* __restrict__ out)
{
    __shared__ float u[AD];
    __shared__ float lf[KLIFT];
    const int b = blockIdx.x, j = blockIdx.y;
    const int tid = threadIdx.x;
    const int idx = g_topidx[b * KSEL + j];

    {
        float v = x[((size_t)b * TT + idx) * DIN + tid] - g_xmean[b * DIN + tid];
        u[tid] = (v - mu[tid]) / sigma[tid];
    }
    if (tid == 0) {
        float sali = g_sal[b * TT + idx];
        float ms = g_msal[b];
        u[256] = ((sali - ms) - mu[256]) / sigma[256];
        float tn = (float)idx * (1.0f / 4096.0f);
        u[257] = ((tn - 0.4998779296875f) - mu[257]) / sigma[257];
        float ds = (idx == 0) ? 0.f : (sali - g_sal[b * TT + idx - 1]);
        float mds = (g_sal[b * TT + TT - 1] - g_sal[b * TT]) * (1.0f / 4096.0f);
        u[258] = ((ds - mds) - mu[258]) / sigma[258];
    }
    __syncthreads();

    if (tid < KLIFT) {
        float acc = b_lift[tid];
        for (int d = 0; d < AD; d++)
            acc = fmaf(u[d], W_lift[d * KLIFT + tid], acc);
        lf[tid] = acc;
    }
    __syncthreads();

    float* o = out + ((size_t)(b * KSEL + j)) * DMODEL;
    for (int m = tid; m < DMODEL; m += 256) {
        float acc = b_proj[m];
#pragma unroll
        for (int k = 0; k < KLIFT; k++)
            acc = fmaf(lf[k], W_proj[k * DMODEL + m], acc);
        o[m] = acc;
    }
}

// ---------------------------------------------------------------------------
extern "C" void kernel_launch(void* const* d_in, const int* in_sizes, int n_in,
                              void* d_out, int out_size)
{
    const float* x      = (const float*)d_in[0];
    const float* W1     = (const float*)d_in[1];
    const float* b1     = (const float*)d_in[2];
    const float* w_sal  = (const float*)d_in[5];
    const float* b_sal  = (const float*)d_in[6];
    const float* mu     = (const float*)d_in[7];
    const float* sigma  = (const float*)d_in[8];
    const float* W_lift = (const float*)d_in[9];
    const float* b_lift = (const float*)d_in[10];
    const float* W_proj = (const float*)d_in[11];
    const float* b_proj = (const float*)d_in[12];
    float* out = (float*)d_out;

    // one-time resources (host-side only; no device allocations)
    static cudaStream_t s2 = []() {
        cudaStream_t s; cudaStreamCreateWithFlags(&s, cudaStreamNonBlocking); return s;
    }();
    static cudaEvent_t evF = []() {
        cudaEvent_t e; cudaEventCreateWithFlags(&e, cudaEventDisableTiming); return e;
    }();
    static cudaEvent_t evJ = []() {
        cudaEvent_t e; cudaEventCreateWithFlags(&e, cudaEventDisableTiming); return e;
    }();

    // fork: xmean chain runs concurrently with GEMM+selector
    cudaEventRecord(evF, 0);
    cudaStreamWaitEvent(s2, evF, 0);
    k_xmean_part<<<dim3(BB, 16), 256, 0, s2>>>(x);
    k_xmean_fin<<<BB, 256, 0, s2>>>();
    cudaEventRecord(evJ, s2);

    k_convert_w<<<HID, DIN>>>(W1);
    k_gemm_part<<<dim3((BB * TT) / 128, 4), 256>>>(x, b1, w_sal);
    k_selector<<<BB, 1024>>>(b_sal, out);

    cudaStreamWaitEvent(0, evJ, 0);
    k_tokens<<<dim3(BB, KSEL), 256>>>(x, mu, sigma, W_lift, b_lift, W_proj, b_proj, out);
}

// round 6
// speedup vs baseline: 2.6418x; 1.1046x over previous
#include <cuda_runtime.h>
#include <cuda_bf16.h>
#include <cstdint>
#include <math.h>

#define BB 32
#define TT 4096
#define DIN 256
#define HID 512
#define AD 259
#define KLIFT 64
#define DMODEL 1024
#define KSEL 32
#define PGD_STEPS 60

// ---------------- scratch (device globals; no allocation allowed) ----------
__device__ float g_sal[BB * TT];
__device__ float g_spart[4][BB * TT];        // per-N-tile partial saliency dot
__device__ float g_xpart[16 * BB * DIN];
__device__ float g_xmean[BB * DIN];
__device__ float g_msal[BB];
__device__ int   g_topidx[BB * KSEL];
// W1 pre-fragmented for mma.sync B operand: [n_tile 64][k_chunk 16][lane 32]
// uint2 = (b0, b1) register pair. hi / lo bf16 split.
__device__ uint2 g_BfH[64 * 16 * 32];
__device__ uint2 g_BfL[64 * 16 * 32];

__device__ __forceinline__ uint32_t pack_bf2(__nv_bfloat16 a, __nv_bfloat16 b) {
    return (uint32_t)__bfloat16_as_ushort(a) | ((uint32_t)__bfloat16_as_ushort(b) << 16);
}

// mma.sync m16n8k16 row.col f32.bf16.bf16.f32 (portable PTX, HMMA pipe)
__device__ __forceinline__ void mma_bf16(float* d, const uint32_t* a, const uint32_t* b) {
    asm volatile(
        "mma.sync.aligned.m16n8k16.row.col.f32.bf16.bf16.f32 "
        "{%0,%1,%2,%3}, {%4,%5,%6,%7}, {%8,%9}, {%0,%1,%2,%3};"
        : "+f"(d[0]), "+f"(d[1]), "+f"(d[2]), "+f"(d[3])
        : "r"(a[0]), "r"(a[1]), "r"(a[2]), "r"(a[3]), "r"(b[0]), "r"(b[1]));
}

// ---------------------------------------------------------------------------
// Kernel 0: W1 -> bf16 hi/lo in mma B-fragment order.
// For fragment (nt, kc), lane l: n = nt*8 + (l>>2), k = kc*16 + (l&3)*2.
// b0 = B[n][k..k+1], b1 = B[n][k+8..k+9]  (B = W1^T).
// ---------------------------------------------------------------------------
__global__ void k_convert_w(const float* __restrict__ W1)
{
    const int nt = blockIdx.x, kc = blockIdx.y, l = threadIdx.x;
    const int n = nt * 8 + (l >> 2);
    const int k = kc * 16 + (l & 3) * 2;
    float v00 = W1[(size_t)k * HID + n];
    float v01 = W1[(size_t)(k + 1) * HID + n];
    float v10 = W1[(size_t)(k + 8) * HID + n];
    float v11 = W1[(size_t)(k + 9) * HID + n];
    __nv_bfloat16 h00 = __float2bfloat16(v00), h01 = __float2bfloat16(v01);
    __nv_bfloat16 h10 = __float2bfloat16(v10), h11 = __float2bfloat16(v11);
    __nv_bfloat16 l00 = __float2bfloat16(v00 - __bfloat162float(h00));
    __nv_bfloat16 l01 = __float2bfloat16(v01 - __bfloat162float(h01));
    __nv_bfloat16 l10 = __float2bfloat16(v10 - __bfloat162float(h10));
    __nv_bfloat16 l11 = __float2bfloat16(v11 - __bfloat162float(h11));
    const int o = (nt * 16 + kc) * 32 + l;
    g_BfH[o] = make_uint2(pack_bf2(h00, h01), pack_bf2(h10, h11));
    g_BfL[o] = make_uint2(pack_bf2(l00, l01), pack_bf2(l10, l11));
}

// ---------------------------------------------------------------------------
// Kernel 1: bf16-split GEMM via mma.sync (3 terms: AhBh + AlBh + AhBl)
// CTA tile M=128 x N=128. A through smem (split on the fly, double-buffered);
// B fragments straight from L2-resident pre-fragmented gmem (no B smem).
// Epilogue: partial = sum_n tanh(h + b1[n]) * w_sal[n] over this N-tile.
// ---------------------------------------------------------------------------
__global__ __launch_bounds__(256, 2) void k_gemm_part(
    const float* __restrict__ x, const float* __restrict__ b1,
    const float* __restrict__ w_sal)
{
    __shared__ __align__(16) __nv_bfloat16 sAh[2][128 * 16];
    __shared__ __align__(16) __nv_bfloat16 sAl[2][128 * 16];
    __shared__ float part[4][128];
    __shared__ float sB1[128], sWs[128];

    const int tid = threadIdx.x;
    const int m0 = blockIdx.x * 128;
    const int n0 = blockIdx.y * 128;
    const int lane = tid & 31, wid = tid >> 5;
    const int wm = (wid >> 2) * 64, wn = (wid & 3) * 32;
    const int g = lane >> 2, t = lane & 3;
    const int ntbase = (n0 >> 3) + ((wid & 3) * 4);   // first n-tile for this warp

    if (tid < 128) { sB1[tid] = b1[n0 + tid]; sWs[tid] = w_sal[n0 + tid]; }

    const int arow = tid >> 1, ahalf = tid & 1;

    float acc[4][4][4];
#pragma unroll
    for (int mi = 0; mi < 4; mi++)
#pragma unroll
        for (int ni = 0; ni < 4; ni++)
#pragma unroll
            for (int q = 0; q < 4; q++) acc[mi][ni][q] = 0.f;

    float4 pa0, pa1;
    {
        const float* ap = &x[(size_t)(m0 + arow) * DIN + ahalf * 8];
        pa0 = *(const float4*)(ap);
        pa1 = *(const float4*)(ap + 4);
    }

    for (int s = 0; s < 16; s++) {
        const int buf = s & 1;
        // ---- B fragments for this chunk: coalesced LDG.64 from L2 ----
        uint2 fbh[4], fbl[4];
#pragma unroll
        for (int ni = 0; ni < 4; ni++) {
            const int o = ((ntbase + ni) * 16 + s) * 32 + lane;
            fbh[ni] = g_BfH[o];
            fbl[ni] = g_BfL[o];
        }
        // ---- STS A (prefetched, split on the fly) ----
        {
            float f[8] = {pa0.x, pa0.y, pa0.z, pa0.w, pa1.x, pa1.y, pa1.z, pa1.w};
            uint32_t hw[4], lw[4];
#pragma unroll
            for (int q = 0; q < 4; q++) {
                __nv_bfloat16 h0 = __float2bfloat16(f[q * 2]);
                __nv_bfloat16 h1 = __float2bfloat16(f[q * 2 + 1]);
                __nv_bfloat16 l0 = __float2bfloat16(f[q * 2] - __bfloat162float(h0));
                __nv_bfloat16 l1 = __float2bfloat16(f[q * 2 + 1] - __bfloat162float(h1));
                hw[q] = pack_bf2(h0, h1);
                lw[q] = pack_bf2(l0, l1);
            }
            int soff = arow * 16 + ahalf * 8;
            *(uint4*)&sAh[buf][soff] = make_uint4(hw[0], hw[1], hw[2], hw[3]);
            *(uint4*)&sAl[buf][soff] = make_uint4(lw[0], lw[1], lw[2], lw[3]);
        }
        __syncthreads();
        if (s < 15) {
            const float* ap = &x[(size_t)(m0 + arow) * DIN + (s + 1) * 16 + ahalf * 8];
            pa0 = *(const float4*)(ap);
            pa1 = *(const float4*)(ap + 4);
        }
        const __nv_bfloat16* Ah = sAh[buf];
        const __nv_bfloat16* Al = sAl[buf];

        uint32_t ah[4][4], al[4][4], bh[4][2], bl[4][2];
#pragma unroll
        for (int ni = 0; ni < 4; ni++) {
            bh[ni][0] = fbh[ni].x; bh[ni][1] = fbh[ni].y;
            bl[ni][0] = fbl[ni].x; bl[ni][1] = fbl[ni].y;
        }
#pragma unroll
        for (int mi = 0; mi < 4; mi++) {
            int r0 = (wm + mi * 16 + g) * 16;
            int r1 = r0 + 8 * 16;
            ah[mi][0] = *(const uint32_t*)&Ah[r0 + t * 2];
            ah[mi][1] = *(const uint32_t*)&Ah[r1 + t * 2];
            ah[mi][2] = *(const uint32_t*)&Ah[r0 + 8 + t * 2];
            ah[mi][3] = *(const uint32_t*)&Ah[r1 + 8 + t * 2];
        }
#pragma unroll
        for (int mi = 0; mi < 4; mi++)
#pragma unroll
            for (int ni = 0; ni < 4; ni++)
                mma_bf16(acc[mi][ni], ah[mi], bh[ni]);
#pragma unroll
        for (int mi = 0; mi < 4; mi++)
#pragma unroll
            for (int ni = 0; ni < 4; ni++)
                mma_bf16(acc[mi][ni], ah[mi], bl[ni]);
#pragma unroll
        for (int mi = 0; mi < 4; mi++) {
            int r0 = (wm + mi * 16 + g) * 16;
            int r1 = r0 + 8 * 16;
            al[mi][0] = *(const uint32_t*)&Al[r0 + t * 2];
            al[mi][1] = *(const uint32_t*)&Al[r1 + t * 2];
            al[mi][2] = *(const uint32_t*)&Al[r0 + 8 + t * 2];
            al[mi][3] = *(const uint32_t*)&Al[r1 + 8 + t * 2];
        }
#pragma unroll
        for (int mi = 0; mi < 4; mi++)
#pragma unroll
            for (int ni = 0; ni < 4; ni++)
                mma_bf16(acc[mi][ni], al[mi], bh[ni]);
        __syncthreads();
    }

    // ---- epilogue: tanh + w_sal dot over this CTA's 128 columns ----
    float rsum[4][2];
#pragma unroll
    for (int mi = 0; mi < 4; mi++) { rsum[mi][0] = 0.f; rsum[mi][1] = 0.f; }
#pragma unroll
    for (int mi = 0; mi < 4; mi++)
#pragma unroll
        for (int ni = 0; ni < 4; ni++) {
            int c0 = wn + ni * 8 + t * 2;
            float w0 = sWs[c0], w1 = sWs[c0 + 1];
            float bb0 = sB1[c0], bb1 = sB1[c0 + 1];
            rsum[mi][0] += tanhf(acc[mi][ni][0] + bb0) * w0
                         + tanhf(acc[mi][ni][1] + bb1) * w1;
            rsum[mi][1] += tanhf(acc[mi][ni][2] + bb0) * w0
                         + tanhf(acc[mi][ni][3] + bb1) * w1;
        }
#pragma unroll
    for (int mi = 0; mi < 4; mi++)
#pragma unroll
        for (int sel = 0; sel < 2; sel++) {
            float v = rsum[mi][sel];
            v += __shfl_xor_sync(0xffffffffu, v, 1);
            v += __shfl_xor_sync(0xffffffffu, v, 2);
            if (t == 0) part[wid & 3][wm + mi * 16 + sel * 8 + g] = v;
        }
    __syncthreads();
    if (tid < 128) {
        float v = ((part[0][tid] + part[1][tid]) + part[2][tid]) + part[3][tid];
        g_spart[blockIdx.y][m0 + tid] = v;
    }
}

// ---------------------------------------------------------------------------
// Kernel 2a/2b: mean of x over T per batch (deterministic two-stage)
// ---------------------------------------------------------------------------
__global__ void k_xmean_part(const float* __restrict__ x)
{
    int b = blockIdx.x, ch = blockIdx.y, d = threadIdx.x;
    const float* base = x + ((size_t)b * TT + ch * 256) * DIN + d;
    float acc = 0.f;
    for (int t = 0; t < 256; t++) acc += base[(size_t)t * DIN];
    g_xpart[(ch * BB + b) * DIN + d] = acc;
}
__global__ void k_xmean_fin()
{
    int b = blockIdx.x, d = threadIdx.x;
    float acc = 0.f;
    for (int ch = 0; ch < 16; ch++) acc += g_xpart[(ch * BB + b) * DIN + d];
    g_xmean[b * DIN + d] = acc * (1.0f / TT);
}

// ---------------------------------------------------------------------------
// Kernel 3: fused sal-finalize + PGD selector (warm-started Newton tau,
// 1-sync block reduces), y_star out, mean_sal, exact top-32.
// ---------------------------------------------------------------------------
__global__ __launch_bounds__(1024) void k_selector(
    const float* __restrict__ b_sal, float* __restrict__ d_out)
{
    __shared__ float ysA[TT];
    __shared__ float ysB[TT];
    __shared__ float redS[2][32], redC[2][32];
    __shared__ float redT[2][32];
    __shared__ int   redi[2][32];

    const int b = blockIdx.x;
    const int tid = threadIdx.x;
    const int lane = tid & 31, wid = tid >> 5;
    const int i0 = tid * 4;

    float4 p0 = *(const float4*)&g_spart[0][b * TT + i0];
    float4 p1 = *(const float4*)&g_spart[1][b * TT + i0];
    float4 p2 = *(const float4*)&g_spart[2][b * TT + i0];
    float4 p3 = *(const float4*)&g_spart[3][b * TT + i0];
    const float bs = b_sal[0];
    float s[4];
    {
        float z0 = ((p0.x + p1.x) + p2.x) + p3.x + bs;
        float z1 = ((p0.y + p1.y) + p2.y) + p3.y + bs;
        float z2 = ((p0.z + p1.z) + p2.z) + p3.z + bs;
        float z3 = ((p0.w + p1.w) + p2.w) + p3.w + bs;
        s[0] = fmaxf(z0, 0.f) + log1pf(expf(-fabsf(z0)));
        s[1] = fmaxf(z1, 0.f) + log1pf(expf(-fabsf(z1)));
        s[2] = fmaxf(z2, 0.f) + log1pf(expf(-fabsf(z2)));
        s[3] = fmaxf(z3, 0.f) + log1pf(expf(-fabsf(z3)));
    }
    *(float4*)&g_sal[b * TT + i0] = make_float4(s[0], s[1], s[2], s[3]);

    float y[4] = {0.0078125f, 0.0078125f, 0.0078125f, 0.0078125f};
    ysA[i0] = y[0]; ysA[i0 + 1] = y[1]; ysA[i0 + 2] = y[2]; ysA[i0 + 3] = y[3];
    __syncthreads();

    float tau_prev = 0.f;
    for (int step = 0; step < PGD_STEPS; step++) {
        const float* rd = (step & 1) ? ysB : ysA;
        float*       wr = (step & 1) ? ysA : ysB;
        float l1 = (i0 > 0) ? rd[i0 - 1] : 0.f;
        float l2 = (i0 > 0) ? rd[i0 - 2] : 0.f;
        float r1 = (i0 + 4 < TT) ? rd[i0 + 4] : 0.f;
        float r2 = (i0 + 4 < TT) ? rd[i0 + 5] : 0.f;
        float nb[4];
        nb[0] = ((y[1] + l1) + y[2]) + l2;
        nb[1] = ((y[2] + y[0]) + y[3]) + l1;
        nb[2] = ((y[3] + y[1]) + r1) + y[0];
        nb[3] = ((r1 + y[2]) + r2) + y[1];

        float z[4];
#pragma unroll
        for (int q = 0; q < 4; q++) {
            float g = (s[q] - y[q]) - 0.5f * nb[q];
            z[q] = fminf(fmaxf(y[q] + 0.1f * g, 0.f), 1.f);
        }

        float tau = tau_prev;
        for (int it = 0; it < 24; it++) {
            const int p = it & 1;
            float ls = 0.f, lc = 0.f;
#pragma unroll
            for (int q = 0; q < 4; q++)
                if (z[q] > tau) { ls += z[q]; lc += 1.f; }
#pragma unroll
            for (int o = 16; o; o >>= 1) {
                ls += __shfl_xor_sync(0xffffffffu, ls, o);
                lc += __shfl_xor_sync(0xffffffffu, lc, o);
            }
            if (lane == 0) { redS[p][wid] = ls; redC[p][wid] = lc; }
            __syncthreads();
            float S = redS[p][lane], C = redC[p][lane];
#pragma unroll
            for (int o = 16; o; o >>= 1) {
                S += __shfl_xor_sync(0xffffffffu, S, o);
                C += __shfl_xor_sync(0xffffffffu, C, o);
            }
            float tnew = (C >= 1.f) ? fmaxf((S - 32.f) / C, 0.f) : 0.f;
            if (tnew == tau) break;
            tau = tnew;
        }
        tau_prev = tau;
#pragma unroll
        for (int q = 0; q < 4; q++)
            y[q] = fminf(fmaxf(z[q] - tau, 0.f), 1.f);
        wr[i0] = y[0]; wr[i0 + 1] = y[1]; wr[i0 + 2] = y[2]; wr[i0 + 3] = y[3];
        __syncthreads();
    }

    float* outY = d_out + (size_t)BB * KSEL * DMODEL + (size_t)b * TT;
    *(float4*)&outY[i0] = make_float4(y[0], y[1], y[2], y[3]);

    {
        float ms = ((s[0] + s[1]) + s[2]) + s[3];
#pragma unroll
        for (int o = 16; o; o >>= 1) ms += __shfl_xor_sync(0xffffffffu, ms, o);
        if (lane == 0) redS[0][wid] = ms;
        __syncthreads();
        if (tid < 32) {
            float v = redS[0][lane];
#pragma unroll
            for (int o = 16; o; o >>= 1) v += __shfl_xor_sync(0xffffffffu, v, o);
            if (lane == 0) g_msal[b] = v * (1.0f / TT);
        }
        __syncthreads();
    }

    float mval[4] = {y[0], y[1], y[2], y[3]};
    for (int sel = 0; sel < KSEL; sel++) {
        const int p = sel & 1;
        float bv = -1.f; int bi = TT;
#pragma unroll
        for (int q = 0; q < 4; q++)
            if (mval[q] > bv) { bv = mval[q]; bi = i0 + q; }
#pragma unroll
        for (int o = 16; o; o >>= 1) {
            float ov = __shfl_xor_sync(0xffffffffu, bv, o);
            int   oi = __shfl_xor_sync(0xffffffffu, bi, o);
            if (ov > bv || (ov == bv && oi < bi)) { bv = ov; bi = oi; }
        }
        if (lane == 0) { redT[p][wid] = bv; redi[p][wid] = bi; }
        __syncthreads();
        bv = redT[p][lane]; bi = redi[p][lane];
#pragma unroll
        for (int o = 16; o; o >>= 1) {
            float ov = __shfl_xor_sync(0xffffffffu, bv, o);
            int   oi = __shfl_xor_sync(0xffffffffu, bi, o);
            if (ov > bv || (ov == bv && oi < bi)) { bv = ov; bi = oi; }
        }
        if (tid == 0) g_topidx[b * KSEL + sel] = bi;
        if ((bi >> 2) == tid) mval[bi & 3] = -1.f;
    }
}

// ---------------------------------------------------------------------------
// Kernel 4: gather -> anchor vector -> lift (259->64) -> project (64->1024)
// ---------------------------------------------------------------------------
__global__ __launch_bounds__(256) void k_tokens(
    const float* __restrict__ x, const float* __restrict__ mu,
    const float* __restrict__ sigma, const float* __restrict__ W_lift,
    const float* __restrict__ b_lift, const float* __restrict__ W_proj,
    const float* __restrict__ b_proj, float* __restrict__ out)
{
    __shared__ float u[AD];
    __shared__ float lf[KLIFT];
    const int b = blockIdx.x, j = blockIdx.y;
    const int tid = threadIdx.x;
    const int idx = g_topidx[b * KSEL + j];

    {
        float v = x[((size_t)b * TT + idx) * DIN + tid] - g_xmean[b * DIN + tid];
        u[tid] = (v - mu[tid]) / sigma[tid];
    }
    if (tid == 0) {
        float sali = g_sal[b * TT + idx];
        float ms = g_msal[b];
        u[256] = ((sali - ms) - mu[256]) / sigma[256];
        float tn = (float)idx * (1.0f / 4096.0f);
        u[257] = ((tn - 0.4998779296875f) - mu[257]) / sigma[257];
        float ds = (idx == 0) ? 0.f : (sali - g_sal[b * TT + idx - 1]);
        float mds = (g_sal[b * TT + TT - 1] - g_sal[b * TT]) * (1.0f / 4096.0f);
        u[258] = ((ds - mds) - mu[258]) / sigma[258];
    }
    __syncthreads();

    if (tid < KLIFT) {
        float acc = b_lift[tid];
        for (int d = 0; d < AD; d++)
            acc = fmaf(u[d], W_lift[d * KLIFT + tid], acc);
        lf[tid] = acc;
    }
    __syncthreads();

    float* o = out + ((size_t)(b * KSEL + j)) * DMODEL;
    for (int m = tid; m < DMODEL; m += 256) {
        float acc = b_proj[m];
#pragma unroll
        for (int k = 0; k < KLIFT; k++)
            acc = fmaf(lf[k], W_proj[k * DMODEL + m], acc);
        o[m] = acc;
    }
}

// ---------------------------------------------------------------------------
extern "C" void kernel_launch(void* const* d_in, const int* in_sizes, int n_in,
                              void* d_out, int out_size)
{
    const float* x      = (const float*)d_in[0];
    const float* W1     = (const float*)d_in[1];
    const float* b1     = (const float*)d_in[2];
    const float* w_sal  = (const float*)d_in[5];
    const float* b_sal  = (const float*)d_in[6];
    const float* mu     = (const float*)d_in[7];
    const float* sigma  = (const float*)d_in[8];
    const float* W_lift = (const float*)d_in[9];
    const float* b_lift = (const float*)d_in[10];
    const float* W_proj = (const float*)d_in[11];
    const float* b_proj = (const float*)d_in[12];
    float* out = (float*)d_out;

    static cudaStream_t s2 = []() {
        cudaStream_t s; cudaStreamCreateWithFlags(&s, cudaStreamNonBlocking); return s;
    }();
    static cudaEvent_t evF = []() {
        cudaEvent_t e; cudaEventCreateWithFlags(&e, cudaEventDisableTiming); return e;
    }();
    static cudaEvent_t evJ = []() {
        cudaEvent_t e; cudaEventCreateWithFlags(&e, cudaEventDisableTiming); return e;
    }();

    cudaEventRecord(evF, 0);
    cudaStreamWaitEvent(s2, evF, 0);
    k_xmean_part<<<dim3(BB, 16), 256, 0, s2>>>(x);
    k_xmean_fin<<<BB, 256, 0, s2>>>();
    cudaEventRecord(evJ, s2);

    k_convert_w<<<dim3(64, 16), 32>>>(W1);
    k_gemm_part<<<dim3((BB * TT) / 128, 4), 256>>>(x, b1, w_sal);
    k_selector<<<BB, 1024>>>(b_sal, out);

    cudaStreamWaitEvent(0, evJ, 0);
    k_tokens<<<dim3(BB, KSEL), 256>>>(x, mu, sigma, W_lift, b_lift, W_proj, b_proj, out);
}

// round 7
// speedup vs baseline: 2.9645x; 1.1222x over previous
#include <cuda_runtime.h>
#include <cuda_bf16.h>
#include <cstdint>
#include <math.h>

#define BB 32
#define TT 4096
#define DIN 256
#define HID 512
#define AD 259
#define KLIFT 64
#define DMODEL 1024
#define KSEL 32
#define PGD_STEPS 60

// ---------------- scratch (device globals; no allocation allowed) ----------
__device__ float g_sal[BB * TT];
__device__ float g_spart[4][BB * TT];        // per-N-tile partial saliency dot
__device__ float g_xpart[16 * BB * DIN];
__device__ float g_xmean[BB * DIN];
__device__ float g_msal[BB];
__device__ int   g_topidx[BB * KSEL];
// W1 pre-fragmented for mma.sync B operand: [n_tile 64][k_chunk 16][lane 32]
__device__ uint2 g_BfH[64 * 16 * 32];
__device__ uint2 g_BfL[64 * 16 * 32];

__device__ __forceinline__ uint32_t pack_bf2(__nv_bfloat16 a, __nv_bfloat16 b) {
    return (uint32_t)__bfloat16_as_ushort(a) | ((uint32_t)__bfloat16_as_ushort(b) << 16);
}

// mma.sync m16n8k16 row.col f32.bf16.bf16.f32 (portable PTX, HMMA pipe)
__device__ __forceinline__ void mma_bf16(float* d, const uint32_t* a, const uint32_t* b) {
    asm volatile(
        "mma.sync.aligned.m16n8k16.row.col.f32.bf16.bf16.f32 "
        "{%0,%1,%2,%3}, {%4,%5,%6,%7}, {%8,%9}, {%0,%1,%2,%3};"
        : "+f"(d[0]), "+f"(d[1]), "+f"(d[2]), "+f"(d[3])
        : "r"(a[0]), "r"(a[1]), "r"(a[2]), "r"(a[3]), "r"(b[0]), "r"(b[1]));
}

// ldmatrix x4: loads 4 8x8 b16 matrices; lane supplies one 16B row address.
__device__ __forceinline__ void ldsm_x4(uint32_t* r, uint32_t saddr) {
    asm volatile(
        "ldmatrix.sync.aligned.m8n8.x4.shared.b16 {%0,%1,%2,%3}, [%4];"
        : "=r"(r[0]), "=r"(r[1]), "=r"(r[2]), "=r"(r[3]) : "r"(saddr));
}

__device__ __forceinline__ uint32_t smem_u32(const void* p) {
    return (uint32_t)__cvta_generic_to_shared(p);
}
// 16B-unit swizzle: distinct banks for all STS/LDSM phases
__device__ __forceinline__ uint32_t su16(uint32_t u) { return u ^ ((u >> 3) & 1u); }

// ---------------------------------------------------------------------------
// Kernel 0: W1 -> bf16 hi/lo in mma B-fragment order.
// ---------------------------------------------------------------------------
__global__ void k_convert_w(const float* __restrict__ W1)
{
    const int nt = blockIdx.x, kc = blockIdx.y, l = threadIdx.x;
    const int n = nt * 8 + (l >> 2);
    const int k = kc * 16 + (l & 3) * 2;
    float v00 = W1[(size_t)k * HID + n];
    float v01 = W1[(size_t)(k + 1) * HID + n];
    float v10 = W1[(size_t)(k + 8) * HID + n];
    float v11 = W1[(size_t)(k + 9) * HID + n];
    __nv_bfloat16 h00 = __float2bfloat16(v00), h01 = __float2bfloat16(v01);
    __nv_bfloat16 h10 = __float2bfloat16(v10), h11 = __float2bfloat16(v11);
    __nv_bfloat16 l00 = __float2bfloat16(v00 - __bfloat162float(h00));
    __nv_bfloat16 l01 = __float2bfloat16(v01 - __bfloat162float(h01));
    __nv_bfloat16 l10 = __float2bfloat16(v10 - __bfloat162float(h10));
    __nv_bfloat16 l11 = __float2bfloat16(v11 - __bfloat162float(h11));
    const int o = (nt * 16 + kc) * 32 + l;
    g_BfH[o] = make_uint2(pack_bf2(h00, h01), pack_bf2(h10, h11));
    g_BfL[o] = make_uint2(pack_bf2(l00, l01), pack_bf2(l10, l11));
}

// ---------------------------------------------------------------------------
// Kernel 1: bf16-split GEMM via mma.sync (AhBh + AlBh + AhBl)
// A in swizzled smem, fragments via ldmatrix.x4; B fragments from L2 gmem.
// ---------------------------------------------------------------------------
__global__ __launch_bounds__(256, 2) void k_gemm_part(
    const float* __restrict__ x, const float* __restrict__ b1,
    const float* __restrict__ w_sal)
{
    // [buf][hi=0/lo=1][256 units of 16B]  (128 rows x 2 units/row)
    __shared__ __align__(16) unsigned char sA[2][2][4096];
    __shared__ float part[4][128];
    __shared__ float sB1[128], sWs[128];

    const int tid = threadIdx.x;
    const int m0 = blockIdx.x * 128;
    const int n0 = blockIdx.y * 128;
    const int lane = tid & 31, wid = tid >> 5;
    const int wm = (wid >> 2) * 64, wn = (wid & 3) * 32;
    const int g = lane >> 2, t = lane & 3;
    const int ntbase = (n0 >> 3) + ((wid & 3) * 4);

    if (tid < 128) { sB1[tid] = b1[n0 + tid]; sWs[tid] = w_sal[n0 + tid]; }

    const int arow = tid >> 1, ahalf = tid & 1;
    const uint32_t stsOff = su16((uint32_t)(arow * 2 + ahalf)) * 16;

    // ldmatrix per-lane fragment offsets (bytes), one per mi
    uint32_t frOff[4];
    {
        const int r8 = lane & 7, hr = (lane >> 3) & 1, hc = (lane >> 4) & 1;
#pragma unroll
        for (int mi = 0; mi < 4; mi++) {
            uint32_t row = (uint32_t)(wm + mi * 16 + hr * 8 + r8);
            frOff[mi] = su16(row * 2 + (uint32_t)hc) * 16;
        }
    }
    const uint32_t baseH[2] = {smem_u32(&sA[0][0][0]), smem_u32(&sA[1][0][0])};
    const uint32_t baseL[2] = {smem_u32(&sA[0][1][0]), smem_u32(&sA[1][1][0])};

    float acc[4][4][4];
#pragma unroll
    for (int mi = 0; mi < 4; mi++)
#pragma unroll
        for (int ni = 0; ni < 4; ni++)
#pragma unroll
            for (int q = 0; q < 4; q++) acc[mi][ni][q] = 0.f;

    float4 pa0, pa1;
    {
        const float* ap = &x[(size_t)(m0 + arow) * DIN + ahalf * 8];
        pa0 = *(const float4*)(ap);
        pa1 = *(const float4*)(ap + 4);
    }

    for (int s = 0; s < 16; s++) {
        const int buf = s & 1;
        // ---- B fragments for this chunk: coalesced LDG.64 from L2 ----
        uint2 fbh[4], fbl[4];
#pragma unroll
        for (int ni = 0; ni < 4; ni++) {
            const int o = ((ntbase + ni) * 16 + s) * 32 + lane;
            fbh[ni] = g_BfH[o];
            fbl[ni] = g_BfL[o];
        }
        // ---- STS A (prefetched, split on the fly, swizzled) ----
        {
            float f[8] = {pa0.x, pa0.y, pa0.z, pa0.w, pa1.x, pa1.y, pa1.z, pa1.w};
            uint32_t hw[4], lw[4];
#pragma unroll
            for (int q = 0; q < 4; q++) {
                __nv_bfloat16 h0 = __float2bfloat16(f[q * 2]);
                __nv_bfloat16 h1 = __float2bfloat16(f[q * 2 + 1]);
                __nv_bfloat16 l0 = __float2bfloat16(f[q * 2] - __bfloat162float(h0));
                __nv_bfloat16 l1 = __float2bfloat16(f[q * 2 + 1] - __bfloat162float(h1));
                hw[q] = pack_bf2(h0, h1);
                lw[q] = pack_bf2(l0, l1);
            }
            *(uint4*)&sA[buf][0][stsOff] = make_uint4(hw[0], hw[1], hw[2], hw[3]);
            *(uint4*)&sA[buf][1][stsOff] = make_uint4(lw[0], lw[1], lw[2], lw[3]);
        }
        __syncthreads();
        if (s < 15) {
            const float* ap = &x[(size_t)(m0 + arow) * DIN + (s + 1) * 16 + ahalf * 8];
            pa0 = *(const float4*)(ap);
            pa1 = *(const float4*)(ap + 4);
        }

        uint32_t bh[4][2], bl[4][2];
#pragma unroll
        for (int ni = 0; ni < 4; ni++) {
            bh[ni][0] = fbh[ni].x; bh[ni][1] = fbh[ni].y;
            bl[ni][0] = fbl[ni].x; bl[ni][1] = fbl[ni].y;
        }
        uint32_t ah[4][4], al[4][4];
#pragma unroll
        for (int mi = 0; mi < 4; mi++) ldsm_x4(ah[mi], baseH[buf] + frOff[mi]);
#pragma unroll
        for (int mi = 0; mi < 4; mi++)
#pragma unroll
            for (int ni = 0; ni < 4; ni++)
                mma_bf16(acc[mi][ni], ah[mi], bh[ni]);
#pragma unroll
        for (int mi = 0; mi < 4; mi++)
#pragma unroll
            for (int ni = 0; ni < 4; ni++)
                mma_bf16(acc[mi][ni], ah[mi], bl[ni]);
#pragma unroll
        for (int mi = 0; mi < 4; mi++) ldsm_x4(al[mi], baseL[buf] + frOff[mi]);
#pragma unroll
        for (int mi = 0; mi < 4; mi++)
#pragma unroll
            for (int ni = 0; ni < 4; ni++)
                mma_bf16(acc[mi][ni], al[mi], bh[ni]);
        __syncthreads();
    }

    // ---- epilogue: tanh + w_sal dot over this CTA's 128 columns ----
    float rsum[4][2];
#pragma unroll
    for (int mi = 0; mi < 4; mi++) { rsum[mi][0] = 0.f; rsum[mi][1] = 0.f; }
#pragma unroll
    for (int mi = 0; mi < 4; mi++)
#pragma unroll
        for (int ni = 0; ni < 4; ni++) {
            int c0 = wn + ni * 8 + t * 2;
            float w0 = sWs[c0], w1 = sWs[c0 + 1];
            float bb0 = sB1[c0], bb1 = sB1[c0 + 1];
            rsum[mi][0] += tanhf(acc[mi][ni][0] + bb0) * w0
                         + tanhf(acc[mi][ni][1] + bb1) * w1;
            rsum[mi][1] += tanhf(acc[mi][ni][2] + bb0) * w0
                         + tanhf(acc[mi][ni][3] + bb1) * w1;
        }
#pragma unroll
    for (int mi = 0; mi < 4; mi++)
#pragma unroll
        for (int sel = 0; sel < 2; sel++) {
            float v = rsum[mi][sel];
            v += __shfl_xor_sync(0xffffffffu, v, 1);
            v += __shfl_xor_sync(0xffffffffu, v, 2);
            if (t == 0) part[wid & 3][wm + mi * 16 + sel * 8 + g] = v;
        }
    __syncthreads();
    if (tid < 128) {
        float v = ((part[0][tid] + part[1][tid]) + part[2][tid]) + part[3][tid];
        g_spart[blockIdx.y][m0 + tid] = v;
    }
}

// ---------------------------------------------------------------------------
// Kernel 2a/2b: mean of x over T per batch (deterministic two-stage)
// ---------------------------------------------------------------------------
__global__ void k_xmean_part(const float* __restrict__ x)
{
    int b = blockIdx.x, ch = blockIdx.y, d = threadIdx.x;
    const float* base = x + ((size_t)b * TT + ch * 256) * DIN + d;
    float acc = 0.f;
    for (int t = 0; t < 256; t++) acc += base[(size_t)t * DIN];
    g_xpart[(ch * BB + b) * DIN + d] = acc;
}
__global__ void k_xmean_fin()
{
    int b = blockIdx.x, d = threadIdx.x;
    float acc = 0.f;
    for (int ch = 0; ch < 16; ch++) acc += g_xpart[(ch * BB + b) * DIN + d];
    g_xmean[b * DIN + d] = acc * (1.0f / TT);
}

// ---------------------------------------------------------------------------
// Kernel 3: fused sal-finalize + PGD selector (warm-started Newton tau,
// 1-sync block reduces), y_star out, mean_sal, exact top-32.
// ---------------------------------------------------------------------------
__global__ __launch_bounds__(1024) void k_selector(
    const float* __restrict__ b_sal, float* __restrict__ d_out)
{
    __shared__ float ysA[TT];
    __shared__ float ysB[TT];
    __shared__ float redS[2][32], redC[2][32];
    __shared__ float redT[2][32];
    __shared__ int   redi[2][32];

    const int b = blockIdx.x;
    const int tid = threadIdx.x;
    const int lane = tid & 31, wid = tid >> 5;
    const int i0 = tid * 4;

    float4 p0 = *(const float4*)&g_spart[0][b * TT + i0];
    float4 p1 = *(const float4*)&g_spart[1][b * TT + i0];
    float4 p2 = *(const float4*)&g_spart[2][b * TT + i0];
    float4 p3 = *(const float4*)&g_spart[3][b * TT + i0];
    const float bs = b_sal[0];
    float s[4];
    {
        float z0 = ((p0.x + p1.x) + p2.x) + p3.x + bs;
        float z1 = ((p0.y + p1.y) + p2.y) + p3.y + bs;
        float z2 = ((p0.z + p1.z) + p2.z) + p3.z + bs;
        float z3 = ((p0.w + p1.w) + p2.w) + p3.w + bs;
        s[0] = fmaxf(z0, 0.f) + log1pf(expf(-fabsf(z0)));
        s[1] = fmaxf(z1, 0.f) + log1pf(expf(-fabsf(z1)));
        s[2] = fmaxf(z2, 0.f) + log1pf(expf(-fabsf(z2)));
        s[3] = fmaxf(z3, 0.f) + log1pf(expf(-fabsf(z3)));
    }
    *(float4*)&g_sal[b * TT + i0] = make_float4(s[0], s[1], s[2], s[3]);

    float y[4] = {0.0078125f, 0.0078125f, 0.0078125f, 0.0078125f};
    ysA[i0] = y[0]; ysA[i0 + 1] = y[1]; ysA[i0 + 2] = y[2]; ysA[i0 + 3] = y[3];
    __syncthreads();

    float tau_prev = 0.f;
    for (int step = 0; step < PGD_STEPS; step++) {
        const float* rd = (step & 1) ? ysB : ysA;
        float*       wr = (step & 1) ? ysA : ysB;
        float l1 = (i0 > 0) ? rd[i0 - 1] : 0.f;
        float l2 = (i0 > 0) ? rd[i0 - 2] : 0.f;
        float r1 = (i0 + 4 < TT) ? rd[i0 + 4] : 0.f;
        float r2 = (i0 + 4 < TT) ? rd[i0 + 5] : 0.f;
        float nb[4];
        nb[0] = ((y[1] + l1) + y[2]) + l2;
        nb[1] = ((y[2] + y[0]) + y[3]) + l1;
        nb[2] = ((y[3] + y[1]) + r1) + y[0];
        nb[3] = ((r1 + y[2]) + r2) + y[1];

        float z[4];
#pragma unroll
        for (int q = 0; q < 4; q++) {
            float g = (s[q] - y[q]) - 0.5f * nb[q];
            z[q] = fminf(fmaxf(y[q] + 0.1f * g, 0.f), 1.f);
        }

        float tau = tau_prev;
        for (int it = 0; it < 24; it++) {
            const int p = it & 1;
            float ls = 0.f, lc = 0.f;
#pragma unroll
            for (int q = 0; q < 4; q++)
                if (z[q] > tau) { ls += z[q]; lc += 1.f; }
#pragma unroll
            for (int o = 16; o; o >>= 1) {
                ls += __shfl_xor_sync(0xffffffffu, ls, o);
                lc += __shfl_xor_sync(0xffffffffu, lc, o);
            }
            if (lane == 0) { redS[p][wid] = ls; redC[p][wid] = lc; }
            __syncthreads();
            float S = redS[p][lane], C = redC[p][lane];
#pragma unroll
            for (int o = 16; o; o >>= 1) {
                S += __shfl_xor_sync(0xffffffffu, S, o);
                C += __shfl_xor_sync(0xffffffffu, C, o);
            }
            float tnew = (C >= 1.f) ? fmaxf((S - 32.f) / C, 0.f) : 0.f;
            if (tnew == tau) break;
            tau = tnew;
        }
        tau_prev = tau;
#pragma unroll
        for (int q = 0; q < 4; q++)
            y[q] = fminf(fmaxf(z[q] - tau, 0.f), 1.f);
        wr[i0] = y[0]; wr[i0 + 1] = y[1]; wr[i0 + 2] = y[2]; wr[i0 + 3] = y[3];
        __syncthreads();
    }

    float* outY = d_out + (size_t)BB * KSEL * DMODEL + (size_t)b * TT;
    *(float4*)&outY[i0] = make_float4(y[0], y[1], y[2], y[3]);

    {
        float ms = ((s[0] + s[1]) + s[2]) + s[3];
#pragma unroll
        for (int o = 16; o; o >>= 1) ms += __shfl_xor_sync(0xffffffffu, ms, o);
        if (lane == 0) redS[0][wid] = ms;
        __syncthreads();
        if (tid < 32) {
            float v = redS[0][lane];
#pragma unroll
            for (int o = 16; o; o >>= 1) v += __shfl_xor_sync(0xffffffffu, v, o);
            if (lane == 0) g_msal[b] = v * (1.0f / TT);
        }
        __syncthreads();
    }

    float mval[4] = {y[0], y[1], y[2], y[3]};
    for (int sel = 0; sel < KSEL; sel++) {
        const int p = sel & 1;
        float bv = -1.f; int bi = TT;
#pragma unroll
        for (int q = 0; q < 4; q++)
            if (mval[q] > bv) { bv = mval[q]; bi = i0 + q; }
#pragma unroll
        for (int o = 16; o; o >>= 1) {
            float ov = __shfl_xor_sync(0xffffffffu, bv, o);
            int   oi = __shfl_xor_sync(0xffffffffu, bi, o);
            if (ov > bv || (ov == bv && oi < bi)) { bv = ov; bi = oi; }
        }
        if (lane == 0) { redT[p][wid] = bv; redi[p][wid] = bi; }
        __syncthreads();
        bv = redT[p][lane]; bi = redi[p][lane];
#pragma unroll
        for (int o = 16; o; o >>= 1) {
            float ov = __shfl_xor_sync(0xffffffffu, bv, o);
            int   oi = __shfl_xor_sync(0xffffffffu, bi, o);
            if (ov > bv || (ov == bv && oi < bi)) { bv = ov; bi = oi; }
        }
        if (tid == 0) g_topidx[b * KSEL + sel] = bi;
        if ((bi >> 2) == tid) mval[bi & 3] = -1.f;
    }
}

// ---------------------------------------------------------------------------
// Kernel 4: gather -> anchor vector -> lift (259->64) -> project (64->1024)
// ---------------------------------------------------------------------------
__global__ __launch_bounds__(256) void k_tokens(
    const float* __restrict__ x, const float* __restrict__ mu,
    const float* __restrict__ sigma, const float* __restrict__ W_lift,
    const float* __restrict__ b_lift, const float* __restrict__ W_proj,
    const float* __restrict__ b_proj, float* __restrict__ out)
{
    __shared__ float u[AD];
    __shared__ float lf[KLIFT];
    const int b = blockIdx.x, j = blockIdx.y;
    const int tid = threadIdx.x;
    const int idx = g_topidx[b * KSEL + j];

    {
        float v = x[((size_t)b * TT + idx) * DIN + tid] - g_xmean[b * DIN + tid];
        u[tid] = (v - mu[tid]) / sigma[tid];
    }
    if (tid == 0) {
        float sali = g_sal[b * TT + idx];
        float ms = g_msal[b];
        u[256] = ((sali - ms) - mu[256]) / sigma[256];
        float tn = (float)idx * (1.0f / 4096.0f);
        u[257] = ((tn - 0.4998779296875f) - mu[257]) / sigma[257];
        float ds = (idx == 0) ? 0.f : (sali - g_sal[b * TT + idx - 1]);
        float mds = (g_sal[b * TT + TT - 1] - g_sal[b * TT]) * (1.0f / 4096.0f);
        u[258] = ((ds - mds) - mu[258]) / sigma[258];
    }
    __syncthreads();

    if (tid < KLIFT) {
        float acc = b_lift[tid];
        for (int d = 0; d < AD; d++)
            acc = fmaf(u[d], W_lift[d * KLIFT + tid], acc);
        lf[tid] = acc;
    }
    __syncthreads();

    float* o = out + ((size_t)(b * KSEL + j)) * DMODEL;
    for (int m = tid; m < DMODEL; m += 256) {
        float acc = b_proj[m];
#pragma unroll
        for (int k = 0; k < KLIFT; k++)
            acc = fmaf(lf[k], W_proj[k * DMODEL + m], acc);
        o[m] = acc;
    }
}

// ---------------------------------------------------------------------------
extern "C" void kernel_launch(void* const* d_in, const int* in_sizes, int n_in,
                              void* d_out, int out_size)
{
    const float* x      = (const float*)d_in[0];
    const float* W1     = (const float*)d_in[1];
    const float* b1     = (const float*)d_in[2];
    const float* w_sal  = (const float*)d_in[5];
    const float* b_sal  = (const float*)d_in[6];
    const float* mu     = (const float*)d_in[7];
    const float* sigma  = (const float*)d_in[8];
    const float* W_lift = (const float*)d_in[9];
    const float* b_lift = (const float*)d_in[10];
    const float* W_proj = (const float*)d_in[11];
    const float* b_proj = (const float*)d_in[12];
    float* out = (float*)d_out;

    static cudaStream_t s2 = []() {
        cudaStream_t s; cudaStreamCreateWithFlags(&s, cudaStreamNonBlocking); return s;
    }();
    static cudaEvent_t evF = []() {
        cudaEvent_t e; cudaEventCreateWithFlags(&e, cudaEventDisableTiming); return e;
    }();
    static cudaEvent_t evJ = []() {
        cudaEvent_t e; cudaEventCreateWithFlags(&e, cudaEventDisableTiming); return e;
    }();

    cudaEventRecord(evF, 0);
    cudaStreamWaitEvent(s2, evF, 0);
    k_xmean_part<<<dim3(BB, 16), 256, 0, s2>>>(x);
    k_xmean_fin<<<BB, 256, 0, s2>>>();
    cudaEventRecord(evJ, s2);

    k_convert_w<<<dim3(64, 16), 32>>>(W1);
    k_gemm_part<<<dim3((BB * TT) / 128, 4), 256>>>(x, b1, w_sal);
    k_selector<<<BB, 1024>>>(b_sal, out);

    cudaStreamWaitEvent(0, evJ, 0);
    k_tokens<<<dim3(BB, KSEL), 256>>>(x, mu, sigma, W_lift, b_lift, W_proj, b_proj, out);
}